// round 5
// baseline (speedup 1.0000x reference)
#include <cuda_runtime.h>
#include <math.h>
#include <stdint.h>

// ---------------------------------------------------------------------------
// Problem constants
// ---------------------------------------------------------------------------
#define SS 2048
#define UU 1024
#define HD 128
#define NHEAD 32
#define MROWS 8192
#define LN_EPS 1e-8f
#define QSCALE 0.08838834764831845f   // 1/sqrt(128)

// ---------------------------------------------------------------------------
// Scratch (device globals; allocation-free rule)
// ---------------------------------------------------------------------------
__device__ float g_xr[(size_t)MROWS * UU];
__device__ float g_wt[4 * (size_t)UU * UU];
__device__ float g_q[(size_t)MROWS * UU];
__device__ float g_k[(size_t)MROWS * UU];
__device__ float g_v[(size_t)MROWS * UU];
__device__ float g_r[(size_t)MROWS * UU];
__device__ float g_attn[(size_t)MROWS * UU];

// ---------------------------------------------------------------------------
// Helpers
// ---------------------------------------------------------------------------
__device__ __forceinline__ uint32_t smem_u32(const void* p) {
    uint32_t a;
    asm("{ .reg .u64 t; cvta.to.shared.u64 t, %1; cvt.u32.u64 %0, t; }" : "=r"(a) : "l"(p));
    return a;
}
__device__ __forceinline__ float rna_tf32(float v) {
    uint32_t u;
    asm("cvt.rna.tf32.f32 %0, %1;" : "=r"(u) : "f"(v));
    return __uint_as_float(u);
}

#define CP_ASYNC16(sa, g) \
    asm volatile("cp.async.cg.shared.global [%0], [%1], 16;" :: "r"(sa), "l"(g))
#define CP_COMMIT() asm volatile("cp.async.commit_group;" ::: "memory")
#define CP_WAIT1()  asm volatile("cp.async.wait_group 1;" ::: "memory")

#define MMA_TF32(d, a, b) \
    asm volatile("mma.sync.aligned.m16n8k8.row.col.f32.tf32.tf32.f32 " \
        "{%0,%1,%2,%3}, {%4,%5,%6,%7}, {%8,%9}, {%0,%1,%2,%3};" \
        : "+f"((d)[0]), "+f"((d)[1]), "+f"((d)[2]), "+f"((d)[3]) \
        : "r"((a)[0]), "r"((a)[1]), "r"((a)[2]), "r"((a)[3]), \
          "r"((b)[0]), "r"((b)[1]))

// ---------------------------------------------------------------------------
// tf32 mma.sync GEMM (validated round 3):  C tile = post( A @ op(B) )
// ---------------------------------------------------------------------------
#define ASTR 36
#define BSTR_NN 132
#define STAGE_WORDS 9216
#define GSMEM (3 * STAGE_WORDS * 4)

template<int BMODE, bool BIASRELU, bool CVT>
__global__ __launch_bounds__(128, 2)
void gemm_mma(const float* __restrict__ A, const float* __restrict__ B,
              const float* __restrict__ bias, float* __restrict__ C,
              int ldA, int ldB, int ldC,
              long long aB, long long bB, long long cB,
              int kIters, float scale)
{
    extern __shared__ float sm[];
    const uint32_t su = smem_u32(sm);
    const int tid = threadIdx.x, lane = tid & 31, wid = tid >> 5;
    const int g = lane >> 2, c = lane & 3;
    const int wm0 = (wid >> 1) * 64, wn0 = (wid & 1) * 64;
    const int z = blockIdx.z;
    const int gm0 = blockIdx.y * 128, gn0 = blockIdx.x * 128;

    const float* Ab = A + (size_t)z * aB + (size_t)gm0 * ldA;
    const float* Bb = B + (size_t)z * bB;

    float acc[4][8][4];
#pragma unroll
    for (int mi = 0; mi < 4; mi++)
#pragma unroll
        for (int ni = 0; ni < 8; ni++)
#pragma unroll
            for (int t = 0; t < 4; t++) acc[mi][ni][t] = 0.f;

    auto load_tile = [&](int i, int s) {
        const uint32_t abase = su + (uint32_t)(s * STAGE_WORDS) * 4;
        const uint32_t bbase = abase + 4608u * 4;
#pragma unroll
        for (int it = 0; it < 8; it++) {
            int chunk = tid + it * 128;
            int row = chunk >> 3, ks = chunk & 7;
            CP_ASYNC16(abase + (uint32_t)(row * ASTR + ks * 4) * 4,
                       Ab + (size_t)row * ldA + i * 32 + ks * 4);
        }
        if (BMODE == 0) {
            const float* Bt = Bb + (size_t)gn0 * ldB;
#pragma unroll
            for (int it = 0; it < 8; it++) {
                int chunk = tid + it * 128;
                int row = chunk >> 3, ks = chunk & 7;
                CP_ASYNC16(bbase + (uint32_t)(row * ASTR + ks * 4) * 4,
                           Bt + (size_t)row * ldB + i * 32 + ks * 4);
            }
        } else {
#pragma unroll
            for (int it = 0; it < 8; it++) {
                int chunk = tid + it * 128;
                int row = chunk >> 5, cs = chunk & 31;
                CP_ASYNC16(bbase + (uint32_t)(row * BSTR_NN + cs * 4) * 4,
                           Bb + (size_t)(i * 32 + row) * ldB + gn0 + cs * 4);
            }
        }
    };

    load_tile(0, 0); CP_COMMIT();
    if (kIters > 1) load_tile(1, 1);
    CP_COMMIT();

    for (int i = 0; i < kIters; i++) {
        CP_WAIT1();
        __syncthreads();
        if (i + 2 < kIters) load_tile(i + 2, (i + 2) % 3);
        CP_COMMIT();

        const float* As_s = sm + (i % 3) * STAGE_WORDS;
        const float* Bs_s = As_s + 4608;

#pragma unroll
        for (int j = 0; j < 4; j++) {
            uint32_t a[4][4], b[8][2];
#pragma unroll
            for (int mi = 0; mi < 4; mi++) {
                const int m = wm0 + mi * 16 + g;
                a[mi][0] = __float_as_uint(As_s[m * ASTR + j * 8 + c]);
                a[mi][1] = __float_as_uint(As_s[(m + 8) * ASTR + j * 8 + c]);
                a[mi][2] = __float_as_uint(As_s[m * ASTR + j * 8 + c + 4]);
                a[mi][3] = __float_as_uint(As_s[(m + 8) * ASTR + j * 8 + c + 4]);
            }
#pragma unroll
            for (int ni = 0; ni < 8; ni++) {
                const int n = wn0 + ni * 8 + g;
                if (BMODE == 0) {
                    b[ni][0] = __float_as_uint(Bs_s[n * ASTR + j * 8 + c]);
                    b[ni][1] = __float_as_uint(Bs_s[n * ASTR + j * 8 + c + 4]);
                } else {
                    b[ni][0] = __float_as_uint(Bs_s[(j * 8 + c) * BSTR_NN + n]);
                    b[ni][1] = __float_as_uint(Bs_s[(j * 8 + c + 4) * BSTR_NN + n]);
                }
            }
#pragma unroll
            for (int mi = 0; mi < 4; mi++)
#pragma unroll
                for (int ni = 0; ni < 8; ni++)
                    MMA_TF32(acc[mi][ni], a[mi], b[ni]);
        }
        __syncthreads();
    }

    float* Cb = C + (size_t)z * cB;
#pragma unroll
    for (int mi = 0; mi < 4; mi++) {
        const int r0 = gm0 + wm0 + mi * 16 + g;
#pragma unroll
        for (int ni = 0; ni < 8; ni++) {
            const int col = gn0 + wn0 + ni * 8 + c * 2;
            float v0 = acc[mi][ni][0], v1 = acc[mi][ni][1];
            float v2 = acc[mi][ni][2], v3 = acc[mi][ni][3];
            if (BIASRELU) {
                float b0 = __ldg(bias + col), b1 = __ldg(bias + col + 1);
                v0 = fmaxf(v0 + b0, 0.f); v1 = fmaxf(v1 + b1, 0.f);
                v2 = fmaxf(v2 + b0, 0.f); v3 = fmaxf(v3 + b1, 0.f);
            }
            v0 *= scale; v1 *= scale; v2 *= scale; v3 *= scale;
            if (CVT) {
                v0 = rna_tf32(v0); v1 = rna_tf32(v1);
                v2 = rna_tf32(v2); v3 = rna_tf32(v3);
            }
            *(float2*)(Cb + (size_t)r0 * ldC + col) = make_float2(v0, v1);
            *(float2*)(Cb + (size_t)(r0 + 8) * ldC + col) = make_float2(v2, v3);
        }
    }
}

// ---------------------------------------------------------------------------
// Fused flash attention: per (q-block of 128, head) CTA.
// 128 threads = 4 warps; each warp owns 32 q-rows x full KV width.
// SMEM: Qs[128][132] resident; K[64][132]/V[64][136] double-buffered.
// P never touches SMEM: exp'd S accumulators are permuted into PV A-fragments
// with register shuffles (lane (g,c) <- lane 4g + c/2, component c&1).
// ---------------------------------------------------------------------------
#define QB 128
#define KB 64
#define QS_STR 132
#define KS_STR 132
#define VS_STR 136
#define PS_STR 36
#define STAGE_FW (KB * KS_STR + KB * VS_STR)          // 17152 words
#define KS_OFF(s) (QB * QS_STR + (s) * STAGE_FW)
#define VS_OFF(s) (KS_OFF(s) + KB * KS_STR)
#define FL_SMEM ((QB * QS_STR + 2 * STAGE_FW) * 4)    // 204800 bytes

__global__ __launch_bounds__(128, 1)
void flash_kernel(const float* __restrict__ q, const float* __restrict__ k,
                  const float* __restrict__ v, float* __restrict__ attn)
{
    extern __shared__ float fs[];
    const uint32_t su = smem_u32(fs);
    const int tid = threadIdx.x, lane = tid & 31, wid = tid >> 5;
    const int g = lane >> 2, c = lane & 3;
    const int h = blockIdx.y, qb = blockIdx.x;
    const int wq0 = wid * 32;

    const float* qh = q + ((size_t)h * SS + (size_t)qb * QB) * HD;
    const float* kh = k + (size_t)h * SS * HD;
    const float* vh = v + (size_t)h * SS * HD;

    // ---- stage Q (128 rows x 128 floats = 4096 16B-chunks) ----
#pragma unroll
    for (int it = 0; it < 32; it++) {
        int idx = tid + it * 128;
        int row = idx >> 5, ks = idx & 31;
        CP_ASYNC16(su + (uint32_t)(row * QS_STR + ks * 4) * 4,
                   qh + (size_t)row * HD + ks * 4);
    }
    CP_COMMIT();

    auto load_kv = [&](int i, int s) {
        const float* kg = kh + (size_t)i * KB * HD;
        const float* vg = vh + (size_t)i * KB * HD;
        const uint32_t kbs = su + (uint32_t)KS_OFF(s) * 4;
        const uint32_t vbs = su + (uint32_t)VS_OFF(s) * 4;
#pragma unroll
        for (int it = 0; it < 16; it++) {          // 64 rows x 32 chunks
            int idx = tid + it * 128;
            int row = idx >> 5, ks = idx & 31;
            CP_ASYNC16(kbs + (uint32_t)(row * KS_STR + ks * 4) * 4,
                       kg + (size_t)row * HD + ks * 4);
        }
#pragma unroll
        for (int it = 0; it < 16; it++) {
            int idx = tid + it * 128;
            int row = idx >> 5, ks = idx & 31;
            CP_ASYNC16(vbs + (uint32_t)(row * VS_STR + ks * 4) * 4,
                       vg + (size_t)row * HD + ks * 4);
        }
    };
    load_kv(0, 0); CP_COMMIT();
    load_kv(1, 1); CP_COMMIT();

    float of[2][16][4];
#pragma unroll
    for (int mi = 0; mi < 2; mi++)
#pragma unroll
        for (int ni = 0; ni < 16; ni++)
#pragma unroll
            for (int t = 0; t < 4; t++) of[mi][ni][t] = 0.f;
    float rm[2][2] = {{-1e30f, -1e30f}, {-1e30f, -1e30f}};
    float rl[2][2] = {{0.f, 0.f}, {0.f, 0.f}};

    const int s1 = (lane & 28) | (c >> 1);   // source lane for P cols c
    const int s2 = s1 + 2;                   // source lane for P cols c+4
    const bool odd = (c & 1);
    const int nIter = SS / KB;   // 32

#pragma unroll 1
    for (int i = 0; i < nIter; i++) {
        const int s = i & 1;
        CP_WAIT1();
        __syncthreads();

        const float* Qs = fs;
        const float* Ks = fs + KS_OFF(s);
        const float* Vs = fs + VS_OFF(s);

        // ---- S = Q(32 rows/warp) @ K^T (64 keys), contraction = HD = 128 ----
        float sacc[2][8][4];
#pragma unroll
        for (int mi = 0; mi < 2; mi++)
#pragma unroll
            for (int ni = 0; ni < 8; ni++)
#pragma unroll
                for (int t = 0; t < 4; t++) sacc[mi][ni][t] = 0.f;

#pragma unroll 4
        for (int j = 0; j < 16; j++) {
            uint32_t a[2][4], b[8][2];
#pragma unroll
            for (int mi = 0; mi < 2; mi++) {
                const int m = wq0 + mi * 16 + g;
                a[mi][0] = __float_as_uint(Qs[m * QS_STR + j * 8 + c]);
                a[mi][1] = __float_as_uint(Qs[(m + 8) * QS_STR + j * 8 + c]);
                a[mi][2] = __float_as_uint(Qs[m * QS_STR + j * 8 + c + 4]);
                a[mi][3] = __float_as_uint(Qs[(m + 8) * QS_STR + j * 8 + c + 4]);
            }
#pragma unroll
            for (int ni = 0; ni < 8; ni++) {
                const int n = ni * 8 + g;
                b[ni][0] = __float_as_uint(Ks[n * KS_STR + j * 8 + c]);
                b[ni][1] = __float_as_uint(Ks[n * KS_STR + j * 8 + c + 4]);
            }
#pragma unroll
            for (int mi = 0; mi < 2; mi++)
#pragma unroll
                for (int ni = 0; ni < 8; ni++)
                    MMA_TF32(sacc[mi][ni], a[mi], b[ni]);
        }

        // ---- online softmax; exp'd rounded P stays in sacc registers ----
        float alpha[2][2];
#pragma unroll
        for (int mi = 0; mi < 2; mi++)
#pragma unroll
            for (int hf = 0; hf < 2; hf++) {
                float mx = -1e30f;
#pragma unroll
                for (int ni = 0; ni < 8; ni++) {
                    mx = fmaxf(mx, sacc[mi][ni][hf * 2]);
                    mx = fmaxf(mx, sacc[mi][ni][hf * 2 + 1]);
                }
                mx = fmaxf(mx, __shfl_xor_sync(0xffffffffu, mx, 1));
                mx = fmaxf(mx, __shfl_xor_sync(0xffffffffu, mx, 2));
                float mn = fmaxf(rm[mi][hf], mx);
                alpha[mi][hf] = __expf(rm[mi][hf] - mn);
                rm[mi][hf] = mn;

                float rs = 0.f;
#pragma unroll
                for (int ni = 0; ni < 8; ni++) {
                    float p0 = __expf(sacc[mi][ni][hf * 2]     - mn);
                    float p1 = __expf(sacc[mi][ni][hf * 2 + 1] - mn);
                    rs += p0 + p1;
                    sacc[mi][ni][hf * 2]     = rna_tf32(p0);
                    sacc[mi][ni][hf * 2 + 1] = rna_tf32(p1);
                }
                rs += __shfl_xor_sync(0xffffffffu, rs, 1);
                rs += __shfl_xor_sync(0xffffffffu, rs, 2);
                rl[mi][hf] = rl[mi][hf] * alpha[mi][hf] + rs;
            }

        // ---- rescale O ----
#pragma unroll
        for (int mi = 0; mi < 2; mi++)
#pragma unroll
            for (int ni = 0; ni < 16; ni++) {
                of[mi][ni][0] *= alpha[mi][0];
                of[mi][ni][1] *= alpha[mi][0];
                of[mi][ni][2] *= alpha[mi][1];
                of[mi][ni][3] *= alpha[mi][1];
            }

        // ---- O += P @ V via shuffle-built A-fragments ----
#pragma unroll 2
        for (int j = 0; j < 8; j++) {
            uint32_t a[2][4];
#pragma unroll
            for (int mi = 0; mi < 2; mi++) {
                float t0 = sacc[mi][j][0], t1 = sacc[mi][j][1];
                float t2 = sacc[mi][j][2], t3 = sacc[mi][j][3];
                float u0a = __shfl_sync(0xffffffffu, t0, s1);
                float u0b = __shfl_sync(0xffffffffu, t1, s1);
                float u1a = __shfl_sync(0xffffffffu, t2, s1);
                float u1b = __shfl_sync(0xffffffffu, t3, s1);
                float u2a = __shfl_sync(0xffffffffu, t0, s2);
                float u2b = __shfl_sync(0xffffffffu, t1, s2);
                float u3a = __shfl_sync(0xffffffffu, t2, s2);
                float u3b = __shfl_sync(0xffffffffu, t3, s2);
                a[mi][0] = __float_as_uint(odd ? u0b : u0a);
                a[mi][1] = __float_as_uint(odd ? u1b : u1a);
                a[mi][2] = __float_as_uint(odd ? u2b : u2a);
                a[mi][3] = __float_as_uint(odd ? u3b : u3a);
            }
#pragma unroll
            for (int nh = 0; nh < 2; nh++) {
                uint32_t b[8][2];
#pragma unroll
                for (int n2 = 0; n2 < 8; n2++) {
                    const int n = nh * 64 + n2 * 8 + g;
                    b[n2][0] = __float_as_uint(Vs[(j * 8 + c) * VS_STR + n]);
                    b[n2][1] = __float_as_uint(Vs[(j * 8 + c + 4) * VS_STR + n]);
                }
#pragma unroll
                for (int mi = 0; mi < 2; mi++)
#pragma unroll
                    for (int n2 = 0; n2 < 8; n2++)
                        MMA_TF32(of[mi][nh * 8 + n2], a[mi], b[n2]);
            }
        }

        __syncthreads();
        if (i + 2 < nIter) load_kv(i + 2, s);
        CP_COMMIT();
    }

    // ---- normalize + write via SMEM transpose (reuse dead KV buffer) ----
    float inv[2][2];
#pragma unroll
    for (int mi = 0; mi < 2; mi++)
#pragma unroll
        for (int hf = 0; hf < 2; hf++) inv[mi][hf] = 1.0f / rl[mi][hf];

    float* Ps = fs + KS_OFF(0);
    float* outb = attn + ((size_t)h * SS + (size_t)qb * QB) * HD;
#pragma unroll 1
    for (int nb = 0; nb < 4; nb++) {
        __syncthreads();
#pragma unroll
        for (int mi = 0; mi < 2; mi++)
#pragma unroll
            for (int hf = 0; hf < 2; hf++) {
                const int prow = wq0 + mi * 16 + hf * 8 + g;
#pragma unroll
                for (int nq = 0; nq < 4; nq++) {
                    const int ni = nb * 4 + nq;
                    *(float2*)(Ps + prow * PS_STR + nq * 8 + 2 * c) =
                        make_float2(of[mi][ni][hf * 2] * inv[mi][hf],
                                    of[mi][ni][hf * 2 + 1] * inv[mi][hf]);
                }
            }
        __syncthreads();
#pragma unroll
        for (int rr = 0; rr < 32; rr++) {
            const int row = rr * 4 + wid;
            outb[(size_t)row * HD + nb * 32 + lane] = Ps[row * PS_STR + lane];
        }
    }
}

// ---------------------------------------------------------------------------
// rna-round copy
// ---------------------------------------------------------------------------
__global__ __launch_bounds__(256)
void roundx_kernel(const float* __restrict__ in, float* __restrict__ out, int n4)
{
    int i = blockIdx.x * 256 + threadIdx.x;
    if (i < n4) {
        float4 v = ((const float4*)in)[i];
        v.x = rna_tf32(v.x); v.y = rna_tf32(v.y);
        v.z = rna_tf32(v.z); v.w = rna_tf32(v.w);
        ((float4*)out)[i] = v;
    }
}

// ---------------------------------------------------------------------------
// Fused epilogue: out = gamma * LN(relu(attn + res)) + beta
// ---------------------------------------------------------------------------
__device__ __forceinline__ float block_sum_256(float v, float* sh)
{
#pragma unroll
    for (int o = 16; o > 0; o >>= 1) v += __shfl_xor_sync(0xffffffffu, v, o);
    if ((threadIdx.x & 31) == 0) sh[threadIdx.x >> 5] = v;
    __syncthreads();
    float t = 0.f;
#pragma unroll
    for (int i = 0; i < 8; i++) t += sh[i];
    __syncthreads();
    return t;
}

__global__ __launch_bounds__(256)
void ln_kernel(const float* __restrict__ attn, const float* __restrict__ res,
               const float* __restrict__ gamma, const float* __restrict__ beta,
               float* __restrict__ out)
{
    __shared__ float sh[8];
    const int tid = threadIdx.x;
    const size_t base = (size_t)blockIdx.x * UU;

    float v[4];
    float s = 0.f;
#pragma unroll
    for (int i = 0; i < 4; i++) {
        int cidx = tid + i * 256;
        float t = fmaxf(attn[base + cidx] + res[base + cidx], 0.f);
        v[i] = t; s += t;
    }
    const float mean = block_sum_256(s, sh) * (1.0f / UU);

    float vs = 0.f;
#pragma unroll
    for (int i = 0; i < 4; i++) { float d = v[i] - mean; vs += d * d; }
    const float var = block_sum_256(vs, sh) * (1.0f / UU);
    const float inv = rsqrtf(var + LN_EPS);

#pragma unroll
    for (int i = 0; i < 4; i++) {
        int cidx = tid + i * 256;
        out[base + cidx] = gamma[cidx] * ((v[i] - mean) * inv) + beta[cidx];
    }
}

// ---------------------------------------------------------------------------
extern "C" void kernel_launch(void* const* d_in, const int* in_sizes, int n_in,
                              void* d_out, int out_size)
{
    const float* x     = (const float*)d_in[0];
    const float* Wq    = (const float*)d_in[1];
    const float* bq    = (const float*)d_in[2];
    const float* Wk    = (const float*)d_in[3];
    const float* bk    = (const float*)d_in[4];
    const float* Wv    = (const float*)d_in[5];
    const float* bv    = (const float*)d_in[6];
    const float* Wr    = (const float*)d_in[7];
    const float* br_   = (const float*)d_in[8];
    const float* gamma = (const float*)d_in[9];
    const float* beta  = (const float*)d_in[10];
    float* out = (float*)d_out;

    float *xr, *wt, *q, *k, *v, *r, *attn;
    cudaGetSymbolAddress((void**)&xr,   g_xr);
    cudaGetSymbolAddress((void**)&wt,   g_wt);
    cudaGetSymbolAddress((void**)&q,    g_q);
    cudaGetSymbolAddress((void**)&k,    g_k);
    cudaGetSymbolAddress((void**)&v,    g_v);
    cudaGetSymbolAddress((void**)&r,    g_r);
    cudaGetSymbolAddress((void**)&attn, g_attn);

    cudaFuncSetAttribute(gemm_mma<1, true,  true >, cudaFuncAttributeMaxDynamicSharedMemorySize, GSMEM);
    cudaFuncSetAttribute(gemm_mma<1, true,  false>, cudaFuncAttributeMaxDynamicSharedMemorySize, GSMEM);
    cudaFuncSetAttribute(flash_kernel, cudaFuncAttributeMaxDynamicSharedMemorySize, FL_SMEM);

    // 1) tf32-round x and weights
    roundx_kernel<<<(MROWS * UU / 4 + 255) / 256, 256>>>(x, xr, MROWS * UU / 4);
    roundx_kernel<<<(UU * UU / 4 + 255) / 256, 256>>>(Wq, wt + 0 * (size_t)UU * UU, UU * UU / 4);
    roundx_kernel<<<(UU * UU / 4 + 255) / 256, 256>>>(Wk, wt + 1 * (size_t)UU * UU, UU * UU / 4);
    roundx_kernel<<<(UU * UU / 4 + 255) / 256, 256>>>(Wv, wt + 2 * (size_t)UU * UU, UU * UU / 4);
    roundx_kernel<<<(UU * UU / 4 + 255) / 256, 256>>>(Wr, wt + 3 * (size_t)UU * UU, UU * UU / 4);

    // 2) projections: relu(x @ W + b); q scaled by 1/sqrt(HD); q/k/v tf32-rounded
    {
        dim3 gr(UU / 128, MROWS / 128, 1);
        gemm_mma<1, true, true ><<<gr, 128, GSMEM>>>(xr, wt + 0 * (size_t)UU * UU, bq,  q, UU, UU, UU, 0, 0, 0, UU / 32, QSCALE);
        gemm_mma<1, true, true ><<<gr, 128, GSMEM>>>(xr, wt + 1 * (size_t)UU * UU, bk,  k, UU, UU, UU, 0, 0, 0, UU / 32, 1.0f);
        gemm_mma<1, true, true ><<<gr, 128, GSMEM>>>(xr, wt + 2 * (size_t)UU * UU, bv,  v, UU, UU, UU, 0, 0, 0, UU / 32, 1.0f);
        gemm_mma<1, true, false><<<gr, 128, GSMEM>>>(xr, wt + 3 * (size_t)UU * UU, br_, r, UU, UU, UU, 0, 0, 0, UU / 32, 1.0f);
    }

    // 3) fused flash attention (replaces scores GEMM + softmax + PV GEMM)
    flash_kernel<<<dim3(SS / QB, NHEAD), 128, FL_SMEM>>>(q, k, v, attn);

    // 4) out = gamma * LN(relu(attn + res)) + beta
    ln_kernel<<<MROWS, 256>>>(attn, r, gamma, beta, out);
}

// round 6
// speedup vs baseline: 3.5461x; 3.5461x over previous
#include <cuda_runtime.h>
#include <cuda_fp16.h>
#include <math.h>
#include <stdint.h>

// ---------------------------------------------------------------------------
// Problem constants
// ---------------------------------------------------------------------------
#define SS 2048
#define UU 1024
#define HD 128
#define NHEAD 32
#define MROWS 8192
#define LN_EPS 1e-8f
#define QSCALE 0.08838834764831845f   // 1/sqrt(128)

// ---------------------------------------------------------------------------
// Scratch (device globals; allocation-free rule)
// ---------------------------------------------------------------------------
__device__ __half g_xh[(size_t)MROWS * UU];
__device__ __half g_wth[4 * (size_t)UU * UU];      // W^T as fp16 [n][k]
__device__ __half g_qh[(size_t)MROWS * UU];
__device__ __half g_kh[(size_t)MROWS * UU];
__device__ __half g_vh[(size_t)MROWS * UU];
__device__ __half g_vt[(size_t)MROWS * UU];        // per-head V^T [d][s]
__device__ float  g_r[(size_t)MROWS * UU];
__device__ float  g_attn[(size_t)MROWS * UU];
__device__ float  g_sc[(size_t)NHEAD * SS * SS];   // scores fp32 (512 MB)
__device__ __half g_p[(size_t)NHEAD * SS * SS];    // softmax'd P fp16 (256 MB)

// ---------------------------------------------------------------------------
// Helpers
// ---------------------------------------------------------------------------
__device__ __forceinline__ uint32_t smem_u32(const void* p) {
    uint32_t a;
    asm("{ .reg .u64 t; cvta.to.shared.u64 t, %1; cvt.u32.u64 %0, t; }" : "=r"(a) : "l"(p));
    return a;
}

#define CP_ASYNC16(sa, g) \
    asm volatile("cp.async.cg.shared.global [%0], [%1], 16;" :: "r"(sa), "l"(g))
#define CP_COMMIT() asm volatile("cp.async.commit_group;" ::: "memory")
#define CP_WAIT1()  asm volatile("cp.async.wait_group 1;" ::: "memory")

#define MMA_F16(d, a, b) \
    asm volatile("mma.sync.aligned.m16n8k16.row.col.f32.f16.f16.f32 " \
        "{%0,%1,%2,%3}, {%4,%5,%6,%7}, {%8,%9}, {%0,%1,%2,%3};" \
        : "+f"((d)[0]), "+f"((d)[1]), "+f"((d)[2]), "+f"((d)[3]) \
        : "r"((a)[0]), "r"((a)[1]), "r"((a)[2]), "r"((a)[3]), \
          "r"((b)[0]), "r"((b)[1]))

// ---------------------------------------------------------------------------
// fp16 NT GEMM:  C[128x128 tile] = post( A @ B^T )
//   A [.,K] half, K-major (ldA); B [N,K] half, K-major (ldB).
// 128 threads = 4 warps (2x2), warp tile 64x64; BK = 64 halfs (128B/row);
// 3-stage cp.async pipeline. SMEM row stride 72 halfs (144B):
// frag reads at byte m*144 + j*32 + 4c -> word 36m+... (4g pattern, 32 banks).
// OUTH: write __half2 (rounds fp32 acc to fp16); else float2.
// ---------------------------------------------------------------------------
#define HSTR 72                       // halfs per SMEM row
#define HROWB 144                     // bytes per SMEM row
#define HA_BYTES (128 * HROWB)        // 18432
#define HSTAGE (2 * HA_BYTES)         // 36864 (A + B)
#define HGSMEM (3 * HSTAGE)           // 110592

template<bool BIASRELU, bool OUTH>
__global__ __launch_bounds__(128, 2)
void gemm_h(const __half* __restrict__ A, const __half* __restrict__ B,
            const float* __restrict__ bias, void* __restrict__ Cv,
            int ldA, int ldB, int ldC,
            long long aB, long long bB, long long cB,
            int kIters, float scale)
{
    extern __shared__ __align__(16) char hsm[];
    const uint32_t su = smem_u32(hsm);
    const int tid = threadIdx.x, lane = tid & 31, wid = tid >> 5;
    const int g = lane >> 2, c = lane & 3;
    const int wm0 = (wid >> 1) * 64, wn0 = (wid & 1) * 64;
    const int z = blockIdx.z;
    const int gm0 = blockIdx.y * 128, gn0 = blockIdx.x * 128;

    const __half* Ab = A + (size_t)z * aB + (size_t)gm0 * ldA;
    const __half* Bb = B + (size_t)z * bB + (size_t)gn0 * ldB;

    float acc[4][8][4];
#pragma unroll
    for (int mi = 0; mi < 4; mi++)
#pragma unroll
        for (int ni = 0; ni < 8; ni++)
#pragma unroll
            for (int t = 0; t < 4; t++) acc[mi][ni][t] = 0.f;

    auto load_tile = [&](int i, int s) {
        const uint32_t abase = su + (uint32_t)(s * HSTAGE);
        const uint32_t bbase = abase + HA_BYTES;
#pragma unroll
        for (int it = 0; it < 8; it++) {           // A: 128 rows x 8 x 16B
            int chunk = tid + it * 128;
            int row = chunk >> 3, ks = chunk & 7;
            CP_ASYNC16(abase + (uint32_t)(row * HROWB + ks * 16),
                       Ab + (size_t)row * ldA + i * 64 + ks * 8);
        }
#pragma unroll
        for (int it = 0; it < 8; it++) {           // B: 128 rows x 8 x 16B
            int chunk = tid + it * 128;
            int row = chunk >> 3, ks = chunk & 7;
            CP_ASYNC16(bbase + (uint32_t)(row * HROWB + ks * 16),
                       Bb + (size_t)row * ldB + i * 64 + ks * 8);
        }
    };

    load_tile(0, 0); CP_COMMIT();
    if (kIters > 1) load_tile(1, 1);
    CP_COMMIT();

    for (int i = 0; i < kIters; i++) {
        CP_WAIT1();
        __syncthreads();
        if (i + 2 < kIters) load_tile(i + 2, (i + 2) % 3);
        CP_COMMIT();

        const __half* As_s = (const __half*)(hsm + (i % 3) * HSTAGE);
        const __half* Bs_s = As_s + HA_BYTES / 2;

#pragma unroll
        for (int j = 0; j < 4; j++) {              // four k16 steps
            uint32_t a[4][4], b[8][2];
#pragma unroll
            for (int mi = 0; mi < 4; mi++) {
                const int m = wm0 + mi * 16 + g;
                a[mi][0] = *(const uint32_t*)(As_s + m * HSTR + j * 16 + 2 * c);
                a[mi][1] = *(const uint32_t*)(As_s + (m + 8) * HSTR + j * 16 + 2 * c);
                a[mi][2] = *(const uint32_t*)(As_s + m * HSTR + j * 16 + 2 * c + 8);
                a[mi][3] = *(const uint32_t*)(As_s + (m + 8) * HSTR + j * 16 + 2 * c + 8);
            }
#pragma unroll
            for (int ni = 0; ni < 8; ni++) {
                const int n = wn0 + ni * 8 + g;
                b[ni][0] = *(const uint32_t*)(Bs_s + n * HSTR + j * 16 + 2 * c);
                b[ni][1] = *(const uint32_t*)(Bs_s + n * HSTR + j * 16 + 2 * c + 8);
            }
#pragma unroll
            for (int mi = 0; mi < 4; mi++)
#pragma unroll
                for (int ni = 0; ni < 8; ni++)
                    MMA_F16(acc[mi][ni], a[mi], b[ni]);
        }
        __syncthreads();
    }

    // ---- epilogue ----
#pragma unroll
    for (int mi = 0; mi < 4; mi++) {
        const int r0 = gm0 + wm0 + mi * 16 + g;
#pragma unroll
        for (int ni = 0; ni < 8; ni++) {
            const int col = gn0 + wn0 + ni * 8 + c * 2;
            float v0 = acc[mi][ni][0], v1 = acc[mi][ni][1];
            float v2 = acc[mi][ni][2], v3 = acc[mi][ni][3];
            if (BIASRELU) {
                float b0 = __ldg(bias + col), b1 = __ldg(bias + col + 1);
                v0 = fmaxf(v0 + b0, 0.f); v1 = fmaxf(v1 + b1, 0.f);
                v2 = fmaxf(v2 + b0, 0.f); v3 = fmaxf(v3 + b1, 0.f);
            }
            v0 *= scale; v1 *= scale; v2 *= scale; v3 *= scale;
            if (OUTH) {
                __half* Cb = (__half*)Cv + (size_t)z * cB;
                *(__half2*)(Cb + (size_t)r0 * ldC + col) = __floats2half2_rn(v0, v1);
                *(__half2*)(Cb + (size_t)(r0 + 8) * ldC + col) = __floats2half2_rn(v2, v3);
            } else {
                float* Cb = (float*)Cv + (size_t)z * cB;
                *(float2*)(Cb + (size_t)r0 * ldC + col) = make_float2(v0, v1);
                *(float2*)(Cb + (size_t)(r0 + 8) * ldC + col) = make_float2(v2, v3);
            }
        }
    }
}

// ---------------------------------------------------------------------------
// Prep kernels
// ---------------------------------------------------------------------------
__global__ __launch_bounds__(256)
void cvtx_kernel(const float* __restrict__ in, __half* __restrict__ out, int n4)
{
    int i = blockIdx.x * 256 + threadIdx.x;
    if (i < n4) {
        float4 v = ((const float4*)in)[i];
        ((__half2*)out)[2 * i]     = __floats2half2_rn(v.x, v.y);
        ((__half2*)out)[2 * i + 1] = __floats2half2_rn(v.z, v.w);
    }
}

__global__ __launch_bounds__(256)
void cvtWT_kernel(const float* __restrict__ in, __half* __restrict__ out)
{   // out[n*1024+k] = half(in[k*1024+n])
    __shared__ float t[32][33];
    int k0 = blockIdx.y * 32, n0 = blockIdx.x * 32;
    int tx = threadIdx.x & 31, ty = threadIdx.x >> 5;   // 32 x 8
#pragma unroll
    for (int r = 0; r < 32; r += 8)
        t[ty + r][tx] = in[(size_t)(k0 + ty + r) * UU + n0 + tx];
    __syncthreads();
#pragma unroll
    for (int r = 0; r < 32; r += 8)
        out[(size_t)(n0 + ty + r) * UU + k0 + tx] = __float2half_rn(t[tx][ty + r]);
}

__global__ __launch_bounds__(256)
void transposeV_kernel(const __half* __restrict__ v, __half* __restrict__ vt)
{   // per head h: vt[h][d][s] = v[h][s][d]
    __shared__ float t[32][33];
    int h = blockIdx.z;
    int d0 = blockIdx.x * 32, s0 = blockIdx.y * 32;
    const __half* vh = v + (size_t)h * SS * HD;
    __half* vth = vt + (size_t)h * HD * SS;
    int tx = threadIdx.x & 31, ty = threadIdx.x >> 5;
#pragma unroll
    for (int r = 0; r < 32; r += 8)
        t[ty + r][tx] = __half2float(vh[(size_t)(s0 + ty + r) * HD + d0 + tx]);
    __syncthreads();
#pragma unroll
    for (int r = 0; r < 32; r += 8)
        vth[(size_t)(d0 + ty + r) * SS + s0 + tx] = __float2half_rn(t[tx][ty + r]);
}

// ---------------------------------------------------------------------------
// Row softmax over 2048 fp32 scores -> fp16 probabilities
// ---------------------------------------------------------------------------
__global__ __launch_bounds__(256)
void softmax_kernel(const float* __restrict__ sc, __half* __restrict__ p)
{
    const int tid = threadIdx.x;
    const float* row = sc + (size_t)blockIdx.x * SS;
    __half* prow = p + (size_t)blockIdx.x * SS;

    float x[8];
    float m = -1e30f;
#pragma unroll
    for (int i = 0; i < 8; i++) { x[i] = row[tid + i * 256]; m = fmaxf(m, x[i]); }
#pragma unroll
    for (int o = 16; o > 0; o >>= 1) m = fmaxf(m, __shfl_xor_sync(0xffffffffu, m, o));
    __shared__ float sm1[8];
    if ((tid & 31) == 0) sm1[tid >> 5] = m;
    __syncthreads();
    m = sm1[0];
#pragma unroll
    for (int i = 1; i < 8; i++) m = fmaxf(m, sm1[i]);

    float s = 0.f;
#pragma unroll
    for (int i = 0; i < 8; i++) { x[i] = __expf(x[i] - m); s += x[i]; }
#pragma unroll
    for (int o = 16; o > 0; o >>= 1) s += __shfl_xor_sync(0xffffffffu, s, o);
    __shared__ float ss2[8];
    if ((tid & 31) == 0) ss2[tid >> 5] = s;
    __syncthreads();
    s = 0.f;
#pragma unroll
    for (int i = 0; i < 8; i++) s += ss2[i];

    const float inv = 1.0f / s;
#pragma unroll
    for (int i = 0; i < 8; i++) prow[tid + i * 256] = __float2half_rn(x[i] * inv);
}

// ---------------------------------------------------------------------------
// Fused epilogue: out = gamma * LN(relu(attn + res)) + beta
// ---------------------------------------------------------------------------
__device__ __forceinline__ float block_sum_256(float v, float* sh)
{
#pragma unroll
    for (int o = 16; o > 0; o >>= 1) v += __shfl_xor_sync(0xffffffffu, v, o);
    if ((threadIdx.x & 31) == 0) sh[threadIdx.x >> 5] = v;
    __syncthreads();
    float t = 0.f;
#pragma unroll
    for (int i = 0; i < 8; i++) t += sh[i];
    __syncthreads();
    return t;
}

__global__ __launch_bounds__(256)
void ln_kernel(const float* __restrict__ attn, const float* __restrict__ res,
               const float* __restrict__ gamma, const float* __restrict__ beta,
               float* __restrict__ out)
{
    __shared__ float sh[8];
    const int tid = threadIdx.x;
    const size_t base = (size_t)blockIdx.x * UU;

    float v[4];
    float s = 0.f;
#pragma unroll
    for (int i = 0; i < 4; i++) {
        int cidx = tid + i * 256;
        float t = fmaxf(attn[base + cidx] + res[base + cidx], 0.f);
        v[i] = t; s += t;
    }
    const float mean = block_sum_256(s, sh) * (1.0f / UU);

    float vs = 0.f;
#pragma unroll
    for (int i = 0; i < 4; i++) { float d = v[i] - mean; vs += d * d; }
    const float var = block_sum_256(vs, sh) * (1.0f / UU);
    const float inv = rsqrtf(var + LN_EPS);

#pragma unroll
    for (int i = 0; i < 4; i++) {
        int cidx = tid + i * 256;
        out[base + cidx] = gamma[cidx] * ((v[i] - mean) * inv) + beta[cidx];
    }
}

// ---------------------------------------------------------------------------
extern "C" void kernel_launch(void* const* d_in, const int* in_sizes, int n_in,
                              void* d_out, int out_size)
{
    const float* x     = (const float*)d_in[0];
    const float* Wq    = (const float*)d_in[1];
    const float* bq    = (const float*)d_in[2];
    const float* Wk    = (const float*)d_in[3];
    const float* bk    = (const float*)d_in[4];
    const float* Wv    = (const float*)d_in[5];
    const float* bv    = (const float*)d_in[6];
    const float* Wr    = (const float*)d_in[7];
    const float* br_   = (const float*)d_in[8];
    const float* gamma = (const float*)d_in[9];
    const float* beta  = (const float*)d_in[10];
    float* out = (float*)d_out;

    __half *xh, *wth, *qh, *kh, *vh, *vt, *p;
    float *r, *attn, *sc;
    cudaGetSymbolAddress((void**)&xh,   g_xh);
    cudaGetSymbolAddress((void**)&wth,  g_wth);
    cudaGetSymbolAddress((void**)&qh,   g_qh);
    cudaGetSymbolAddress((void**)&kh,   g_kh);
    cudaGetSymbolAddress((void**)&vh,   g_vh);
    cudaGetSymbolAddress((void**)&vt,   g_vt);
    cudaGetSymbolAddress((void**)&p,    g_p);
    cudaGetSymbolAddress((void**)&r,    g_r);
    cudaGetSymbolAddress((void**)&attn, g_attn);
    cudaGetSymbolAddress((void**)&sc,   g_sc);

    cudaFuncSetAttribute(gemm_h<true,  true >, cudaFuncAttributeMaxDynamicSharedMemorySize, HGSMEM);
    cudaFuncSetAttribute(gemm_h<true,  false>, cudaFuncAttributeMaxDynamicSharedMemorySize, HGSMEM);
    cudaFuncSetAttribute(gemm_h<false, false>, cudaFuncAttributeMaxDynamicSharedMemorySize, HGSMEM);

    // 1) fp16 conversions: x, W^T
    cvtx_kernel<<<(MROWS * UU / 4 + 255) / 256, 256>>>(x, xh, MROWS * UU / 4);
    {
        dim3 g(UU / 32, UU / 32);
        cvtWT_kernel<<<g, 256>>>(Wq, wth + 0 * (size_t)UU * UU);
        cvtWT_kernel<<<g, 256>>>(Wk, wth + 1 * (size_t)UU * UU);
        cvtWT_kernel<<<g, 256>>>(Wv, wth + 2 * (size_t)UU * UU);
        cvtWT_kernel<<<g, 256>>>(Wr, wth + 3 * (size_t)UU * UU);
    }

    // 2) projections: relu(x @ W + b); q pre-scaled by 1/sqrt(HD); q/k/v -> fp16
    {
        dim3 gr(UU / 128, MROWS / 128, 1);
        gemm_h<true, true ><<<gr, 128, HGSMEM>>>(xh, wth + 0 * (size_t)UU * UU, bq,  qh, UU, UU, UU, 0, 0, 0, UU / 64, QSCALE);
        gemm_h<true, true ><<<gr, 128, HGSMEM>>>(xh, wth + 1 * (size_t)UU * UU, bk,  kh, UU, UU, UU, 0, 0, 0, UU / 64, 1.0f);
        gemm_h<true, true ><<<gr, 128, HGSMEM>>>(xh, wth + 2 * (size_t)UU * UU, bv,  vh, UU, UU, UU, 0, 0, 0, UU / 64, 1.0f);
        gemm_h<true, false><<<gr, 128, HGSMEM>>>(xh, wth + 3 * (size_t)UU * UU, br_, r,  UU, UU, UU, 0, 0, 0, UU / 64, 1.0f);
    }

    // 3) per-head V^T (for NT PV GEMM)
    transposeV_kernel<<<dim3(HD / 32, SS / 32, NHEAD), 256>>>(vh, vt);

    // 4) scores = q @ k^T per head -> fp32
    gemm_h<false, false><<<dim3(SS / 128, SS / 128, NHEAD), 128, HGSMEM>>>(
        qh, kh, nullptr, sc, HD, HD, SS,
        (long long)SS * HD, (long long)SS * HD, (long long)SS * SS, HD / 64, 1.0f);

    // 5) softmax: fp32 scores -> fp16 P
    softmax_kernel<<<NHEAD * SS, 256>>>(sc, p);

    // 6) attn = P @ V  (NT with vt[d][s]) -> fp32
    gemm_h<false, false><<<dim3(HD / 128, SS / 128, NHEAD), 128, HGSMEM>>>(
        p, vt, nullptr, attn, SS, SS, HD,
        (long long)SS * SS, (long long)HD * SS, (long long)SS * HD, SS / 64, 1.0f);

    // 7) out = gamma * LN(relu(attn + res)) + beta
    ln_kernel<<<MROWS, 256>>>(attn, r, gamma, beta, out);
}

// round 9
// speedup vs baseline: 4.3878x; 1.2374x over previous
#include <cuda_runtime.h>
#include <cuda_fp16.h>
#include <math.h>
#include <stdint.h>

// ---------------------------------------------------------------------------
// Problem constants
// ---------------------------------------------------------------------------
#define SS 2048
#define UU 1024
#define HD 128
#define NHEAD 32
#define MROWS 8192
#define LN_EPS 1e-8f
#define QSCALE 0.08838834764831845f   // 1/sqrt(128)

// ---------------------------------------------------------------------------
// Scratch (device globals; allocation-free rule)
// ---------------------------------------------------------------------------
__device__ __half g_xh[(size_t)MROWS * UU];
__device__ __half g_wth[4 * (size_t)UU * UU];      // W^T fp16 [n][k]
__device__ __half g_qh[(size_t)MROWS * UU];
__device__ __half g_kh[(size_t)MROWS * UU];
__device__ __half g_vh[(size_t)MROWS * UU];
__device__ __half g_vt[(size_t)MROWS * UU];        // per-head V^T [d][s]
__device__ float  g_r[(size_t)MROWS * UU];
__device__ float  g_attn[(size_t)MROWS * UU];

// ---------------------------------------------------------------------------
// Helpers
// ---------------------------------------------------------------------------
__device__ __forceinline__ uint32_t smem_u32(const void* p) {
    uint32_t a;
    asm("{ .reg .u64 t; cvta.to.shared.u64 t, %1; cvt.u32.u64 %0, t; }" : "=r"(a) : "l"(p));
    return a;
}

#define CP_ASYNC16(sa, g) \
    asm volatile("cp.async.cg.shared.global [%0], [%1], 16;" :: "r"(sa), "l"(g))
#define CP_COMMIT() asm volatile("cp.async.commit_group;" ::: "memory")
#define CP_WAIT1()  asm volatile("cp.async.wait_group 1;" ::: "memory")

#define MMA_F16(d, a, b) \
    asm volatile("mma.sync.aligned.m16n8k16.row.col.f32.f16.f16.f32 " \
        "{%0,%1,%2,%3}, {%4,%5,%6,%7}, {%8,%9}, {%0,%1,%2,%3};" \
        : "+f"((d)[0]), "+f"((d)[1]), "+f"((d)[2]), "+f"((d)[3]) \
        : "r"((a)[0]), "r"((a)[1]), "r"((a)[2]), "r"((a)[3]), \
          "r"((b)[0]), "r"((b)[1]))

// pack two fp32 -> one half2 register (lo -> low half)
__device__ __forceinline__ uint32_t pack_h2(float lo, float hi) {
    uint32_t r;
    asm("cvt.rn.f16x2.f32 %0, %1, %2;" : "=r"(r) : "f"(hi), "f"(lo));
    return r;
}

// ---------------------------------------------------------------------------
// fp16 NT GEMM (validated round 6): C[128x128] = post( A @ B^T )
// ---------------------------------------------------------------------------
#define HSTR 72
#define HROWB 144
#define HA_BYTES (128 * HROWB)
#define HSTAGE (2 * HA_BYTES)
#define HGSMEM (3 * HSTAGE)

template<bool BIASRELU, bool OUTH>
__global__ __launch_bounds__(128, 2)
void gemm_h(const __half* __restrict__ A, const __half* __restrict__ B,
            const float* __restrict__ bias, void* __restrict__ Cv,
            int ldA, int ldB, int ldC,
            long long aB, long long bB, long long cB,
            int kIters, float scale)
{
    extern __shared__ __align__(16) char hsm[];
    const uint32_t su = smem_u32(hsm);
    const int tid = threadIdx.x, lane = tid & 31, wid = tid >> 5;
    const int g = lane >> 2, c = lane & 3;
    const int wm0 = (wid >> 1) * 64, wn0 = (wid & 1) * 64;
    const int z = blockIdx.z;
    const int gm0 = blockIdx.y * 128, gn0 = blockIdx.x * 128;

    const __half* Ab = A + (size_t)z * aB + (size_t)gm0 * ldA;
    const __half* Bb = B + (size_t)z * bB + (size_t)gn0 * ldB;

    float acc[4][8][4];
#pragma unroll
    for (int mi = 0; mi < 4; mi++)
#pragma unroll
        for (int ni = 0; ni < 8; ni++)
#pragma unroll
            for (int t = 0; t < 4; t++) acc[mi][ni][t] = 0.f;

    auto load_tile = [&](int i, int s) {
        const uint32_t abase = su + (uint32_t)(s * HSTAGE);
        const uint32_t bbase = abase + HA_BYTES;
#pragma unroll
        for (int it = 0; it < 8; it++) {
            int chunk = tid + it * 128;
            int row = chunk >> 3, ks = chunk & 7;
            CP_ASYNC16(abase + (uint32_t)(row * HROWB + ks * 16),
                       Ab + (size_t)row * ldA + i * 64 + ks * 8);
        }
#pragma unroll
        for (int it = 0; it < 8; it++) {
            int chunk = tid + it * 128;
            int row = chunk >> 3, ks = chunk & 7;
            CP_ASYNC16(bbase + (uint32_t)(row * HROWB + ks * 16),
                       Bb + (size_t)row * ldB + i * 64 + ks * 8);
        }
    };

    load_tile(0, 0); CP_COMMIT();
    if (kIters > 1) load_tile(1, 1);
    CP_COMMIT();

    for (int i = 0; i < kIters; i++) {
        CP_WAIT1();
        __syncthreads();
        if (i + 2 < kIters) load_tile(i + 2, (i + 2) % 3);
        CP_COMMIT();

        const __half* As_s = (const __half*)(hsm + (i % 3) * HSTAGE);
        const __half* Bs_s = As_s + HA_BYTES / 2;

#pragma unroll
        for (int j = 0; j < 4; j++) {
            uint32_t a[4][4], b[8][2];
#pragma unroll
            for (int mi = 0; mi < 4; mi++) {
                const int m = wm0 + mi * 16 + g;
                a[mi][0] = *(const uint32_t*)(As_s + m * HSTR + j * 16 + 2 * c);
                a[mi][1] = *(const uint32_t*)(As_s + (m + 8) * HSTR + j * 16 + 2 * c);
                a[mi][2] = *(const uint32_t*)(As_s + m * HSTR + j * 16 + 2 * c + 8);
                a[mi][3] = *(const uint32_t*)(As_s + (m + 8) * HSTR + j * 16 + 2 * c + 8);
            }
#pragma unroll
            for (int ni = 0; ni < 8; ni++) {
                const int n = wn0 + ni * 8 + g;
                b[ni][0] = *(const uint32_t*)(Bs_s + n * HSTR + j * 16 + 2 * c);
                b[ni][1] = *(const uint32_t*)(Bs_s + n * HSTR + j * 16 + 2 * c + 8);
            }
#pragma unroll
            for (int mi = 0; mi < 4; mi++)
#pragma unroll
                for (int ni = 0; ni < 8; ni++)
                    MMA_F16(acc[mi][ni], a[mi], b[ni]);
        }
        __syncthreads();
    }

#pragma unroll
    for (int mi = 0; mi < 4; mi++) {
        const int r0 = gm0 + wm0 + mi * 16 + g;
#pragma unroll
        for (int ni = 0; ni < 8; ni++) {
            const int col = gn0 + wn0 + ni * 8 + c * 2;
            float v0 = acc[mi][ni][0], v1 = acc[mi][ni][1];
            float v2 = acc[mi][ni][2], v3 = acc[mi][ni][3];
            if (BIASRELU) {
                float b0 = __ldg(bias + col), b1 = __ldg(bias + col + 1);
                v0 = fmaxf(v0 + b0, 0.f); v1 = fmaxf(v1 + b1, 0.f);
                v2 = fmaxf(v2 + b0, 0.f); v3 = fmaxf(v3 + b1, 0.f);
            }
            v0 *= scale; v1 *= scale; v2 *= scale; v3 *= scale;
            if (OUTH) {
                __half* Cb = (__half*)Cv + (size_t)z * cB;
                *(__half2*)(Cb + (size_t)r0 * ldC + col) = __floats2half2_rn(v0, v1);
                *(__half2*)(Cb + (size_t)(r0 + 8) * ldC + col) = __floats2half2_rn(v2, v3);
            } else {
                float* Cb = (float*)Cv + (size_t)z * cB;
                *(float2*)(Cb + (size_t)r0 * ldC + col) = make_float2(v0, v1);
                *(float2*)(Cb + (size_t)(r0 + 8) * ldC + col) = make_float2(v2, v3);
            }
        }
    }
}

// ---------------------------------------------------------------------------
// fp16 flash attention: grid (16 q-blocks, 32 heads), 256 threads = 8 warps.
// Q/K rows carry the FULL 128-half contraction -> dedicated stride FSTR=136
// halfs (272 B): frag word index = 68m + 8j + c, 68 mod 32 = 4 -> bank
// (4g + c) & 31 covers all 32 banks. V^T rows are 64 halfs -> stride 72.
// PV A-frags packed from exp'd fp32 S-accumulators in registers.
// SMEM: Q 34816 + 2 x (K 17408 + V 18432) = 106496 B -> 2 CTAs/SM.
// ---------------------------------------------------------------------------
#define FQB 128
#define FKB 64
#define FSTR 136
#define FROWB 272
#define FQ_BYTES (FQB * FROWB)                    // 34816
#define FK_BYTES (FKB * FROWB)                    // 17408
#define FV_BYTES (HD * HROWB)                     // 18432 (128 d-rows x 64 halfs)
#define FSTAGE (FK_BYTES + FV_BYTES)              // 35840
#define FKS_OFF(s) (FQ_BYTES + (s) * FSTAGE)
#define FVS_OFF(s) (FKS_OFF(s) + FK_BYTES)
#define FL_SMEM (FQ_BYTES + 2 * FSTAGE)           // 106496

__global__ __launch_bounds__(256, 2)
void flash_h(const __half* __restrict__ q, const __half* __restrict__ k,
             const __half* __restrict__ vt, float* __restrict__ attn)
{
    extern __shared__ __align__(16) char fsm[];
    const uint32_t su = smem_u32(fsm);
    const int tid = threadIdx.x, lane = tid & 31, wid = tid >> 5;
    const int g = lane >> 2, c = lane & 3;
    const int h = blockIdx.y, qb = blockIdx.x;
    const int wq0 = wid * 16;

    const __half* qh = q + ((size_t)h * SS + (size_t)qb * FQB) * HD;
    const __half* kh = k + (size_t)h * SS * HD;
    const __half* vth = vt + (size_t)h * HD * SS;   // [d][s], ld = SS

    // ---- stage Q: 128 rows x 16 chunks of 16B (stride 272 B) ----
#pragma unroll
    for (int it = 0; it < 8; it++) {
        int idx = tid + it * 256;
        int row = idx >> 4, ks = idx & 15;
        CP_ASYNC16(su + (uint32_t)(row * FROWB + ks * 16),
                   qh + (size_t)row * HD + ks * 8);
    }
    CP_COMMIT();

    auto load_kv = [&](int i, int s) {
        const __half* kg = kh + (size_t)i * FKB * HD;
        const __half* vg = vth + (size_t)i * FKB;    // column offset in [d][s]
        const uint32_t kbs = su + (uint32_t)FKS_OFF(s);
        const uint32_t vbs = su + (uint32_t)FVS_OFF(s);
#pragma unroll
        for (int it = 0; it < 4; it++) {             // K: 64 rows x 16 chunks
            int idx = tid + it * 256;
            int row = idx >> 4, ks = idx & 15;
            CP_ASYNC16(kbs + (uint32_t)(row * FROWB + ks * 16),
                       kg + (size_t)row * HD + ks * 8);
        }
#pragma unroll
        for (int it = 0; it < 4; it++) {             // V^T: 128 d-rows x 8 chunks
            int idx = tid + it * 256;
            int row = idx >> 3, ks = idx & 7;
            CP_ASYNC16(vbs + (uint32_t)(row * HROWB + ks * 16),
                       vg + (size_t)row * SS + ks * 8);
        }
    };
    load_kv(0, 0); CP_COMMIT();
    load_kv(1, 1); CP_COMMIT();

    float of[16][4];
#pragma unroll
    for (int ni = 0; ni < 16; ni++)
#pragma unroll
        for (int t = 0; t < 4; t++) of[ni][t] = 0.f;
    float rm[2] = {-1e30f, -1e30f};
    float rl[2] = {0.f, 0.f};

    const int nIter = SS / FKB;   // 32

#pragma unroll 1
    for (int i = 0; i < nIter; i++) {
        const int s = i & 1;
        CP_WAIT1();
        __syncthreads();

        const __half* Qs = (const __half*)fsm;
        const __half* Ks = (const __half*)(fsm + FKS_OFF(s));
        const __half* Vs = (const __half*)(fsm + FVS_OFF(s));

        // ---- S = Q(16 rows) @ K^T(64 keys), contraction HD=128 ----
        float sacc[8][4];
#pragma unroll
        for (int ni = 0; ni < 8; ni++)
#pragma unroll
            for (int t = 0; t < 4; t++) sacc[ni][t] = 0.f;

#pragma unroll
        for (int j = 0; j < 8; j++) {
            uint32_t a[4], b[8][2];
            const int m = wq0 + g;
            a[0] = *(const uint32_t*)(Qs + m * FSTR + j * 16 + 2 * c);
            a[1] = *(const uint32_t*)(Qs + (m + 8) * FSTR + j * 16 + 2 * c);
            a[2] = *(const uint32_t*)(Qs + m * FSTR + j * 16 + 2 * c + 8);
            a[3] = *(const uint32_t*)(Qs + (m + 8) * FSTR + j * 16 + 2 * c + 8);
#pragma unroll
            for (int ni = 0; ni < 8; ni++) {
                const int n = ni * 8 + g;
                b[ni][0] = *(const uint32_t*)(Ks + n * FSTR + j * 16 + 2 * c);
                b[ni][1] = *(const uint32_t*)(Ks + n * FSTR + j * 16 + 2 * c + 8);
            }
#pragma unroll
            for (int ni = 0; ni < 8; ni++)
                MMA_F16(sacc[ni], a, b[ni]);
        }

        // ---- online softmax (rows g, g+8; reduce over c lanes) ----
        float alpha[2];
#pragma unroll
        for (int hf = 0; hf < 2; hf++) {
            float mx = -1e30f;
#pragma unroll
            for (int ni = 0; ni < 8; ni++) {
                mx = fmaxf(mx, sacc[ni][hf * 2]);
                mx = fmaxf(mx, sacc[ni][hf * 2 + 1]);
            }
            mx = fmaxf(mx, __shfl_xor_sync(0xffffffffu, mx, 1));
            mx = fmaxf(mx, __shfl_xor_sync(0xffffffffu, mx, 2));
            float mn = fmaxf(rm[hf], mx);
            alpha[hf] = __expf(rm[hf] - mn);
            rm[hf] = mn;

            float rs = 0.f;
#pragma unroll
            for (int ni = 0; ni < 8; ni++) {
                float p0 = __expf(sacc[ni][hf * 2]     - mn);
                float p1 = __expf(sacc[ni][hf * 2 + 1] - mn);
                rs += p0 + p1;
                sacc[ni][hf * 2]     = p0;
                sacc[ni][hf * 2 + 1] = p1;
            }
            rs += __shfl_xor_sync(0xffffffffu, rs, 1);
            rs += __shfl_xor_sync(0xffffffffu, rs, 2);
            rl[hf] = rl[hf] * alpha[hf] + rs;
        }

        // ---- rescale O ----
#pragma unroll
        for (int ni = 0; ni < 16; ni++) {
            of[ni][0] *= alpha[0];
            of[ni][1] *= alpha[0];
            of[ni][2] *= alpha[1];
            of[ni][3] *= alpha[1];
        }

        // ---- O += P @ V : A-frags packed from sacc (no shuffle/SMEM) ----
#pragma unroll
        for (int jj = 0; jj < 4; jj++) {           // k16 steps over 64 keys
            uint32_t a[4];
            a[0] = pack_h2(sacc[2 * jj][0],     sacc[2 * jj][1]);
            a[1] = pack_h2(sacc[2 * jj][2],     sacc[2 * jj][3]);
            a[2] = pack_h2(sacc[2 * jj + 1][0], sacc[2 * jj + 1][1]);
            a[3] = pack_h2(sacc[2 * jj + 1][2], sacc[2 * jj + 1][3]);
#pragma unroll
            for (int ni = 0; ni < 16; ni++) {
                uint32_t b[2];
                const int n = ni * 8 + g;          // d index
                b[0] = *(const uint32_t*)(Vs + n * HSTR + jj * 16 + 2 * c);
                b[1] = *(const uint32_t*)(Vs + n * HSTR + jj * 16 + 2 * c + 8);
                MMA_F16(of[ni], a, b);
            }
        }

        __syncthreads();
        if (i + 2 < nIter) load_kv(i + 2, s);
        CP_COMMIT();
    }

    // ---- normalize + write ----
    float inv[2] = {1.0f / rl[0], 1.0f / rl[1]};
    float* outb = attn + ((size_t)h * SS + (size_t)qb * FQB + wq0) * HD;
#pragma unroll
    for (int hf = 0; hf < 2; hf++) {
        float* rowp = outb + (size_t)(hf * 8 + g) * HD;
#pragma unroll
        for (int ni = 0; ni < 16; ni++)
            *(float2*)(rowp + ni * 8 + 2 * c) =
                make_float2(of[ni][hf * 2] * inv[hf], of[ni][hf * 2 + 1] * inv[hf]);
    }
}

// ---------------------------------------------------------------------------
// Prep kernels
// ---------------------------------------------------------------------------
__global__ __launch_bounds__(256)
void cvtx_kernel(const float* __restrict__ in, __half* __restrict__ out, int n4)
{
    int i = blockIdx.x * 256 + threadIdx.x;
    if (i < n4) {
        float4 v = ((const float4*)in)[i];
        ((__half2*)out)[2 * i]     = __floats2half2_rn(v.x, v.y);
        ((__half2*)out)[2 * i + 1] = __floats2half2_rn(v.z, v.w);
    }
}

__global__ __launch_bounds__(256)
void cvtWT_kernel(const float* __restrict__ in, __half* __restrict__ out)
{
    __shared__ float t[32][33];
    int k0 = blockIdx.y * 32, n0 = blockIdx.x * 32;
    int tx = threadIdx.x & 31, ty = threadIdx.x >> 5;
#pragma unroll
    for (int r = 0; r < 32; r += 8)
        t[ty + r][tx] = in[(size_t)(k0 + ty + r) * UU + n0 + tx];
    __syncthreads();
#pragma unroll
    for (int r = 0; r < 32; r += 8)
        out[(size_t)(n0 + ty + r) * UU + k0 + tx] = __float2half_rn(t[tx][ty + r]);
}

__global__ __launch_bounds__(256)
void transposeV_kernel(const __half* __restrict__ v, __half* __restrict__ vt)
{
    __shared__ float t[32][33];
    int h = blockIdx.z;
    int d0 = blockIdx.x * 32, s0 = blockIdx.y * 32;
    const __half* vh = v + (size_t)h * SS * HD;
    __half* vth = vt + (size_t)h * HD * SS;
    int tx = threadIdx.x & 31, ty = threadIdx.x >> 5;
#pragma unroll
    for (int r = 0; r < 32; r += 8)
        t[ty + r][tx] = __half2float(vh[(size_t)(s0 + ty + r) * HD + d0 + tx]);
    __syncthreads();
#pragma unroll
    for (int r = 0; r < 32; r += 8)
        vth[(size_t)(d0 + ty + r) * SS + s0 + tx] = __float2half_rn(t[tx][ty + r]);
}

// ---------------------------------------------------------------------------
// Fused epilogue: out = gamma * LN(relu(attn + res)) + beta
// ---------------------------------------------------------------------------
__device__ __forceinline__ float block_sum_256(float v, float* sh)
{
#pragma unroll
    for (int o = 16; o > 0; o >>= 1) v += __shfl_xor_sync(0xffffffffu, v, o);
    if ((threadIdx.x & 31) == 0) sh[threadIdx.x >> 5] = v;
    __syncthreads();
    float t = 0.f;
#pragma unroll
    for (int i = 0; i < 8; i++) t += sh[i];
    __syncthreads();
    return t;
}

__global__ __launch_bounds__(256)
void ln_kernel(const float* __restrict__ attn, const float* __restrict__ res,
               const float* __restrict__ gamma, const float* __restrict__ beta,
               float* __restrict__ out)
{
    __shared__ float sh[8];
    const int tid = threadIdx.x;
    const size_t base = (size_t)blockIdx.x * UU;

    float v[4];
    float s = 0.f;
#pragma unroll
    for (int i = 0; i < 4; i++) {
        int cidx = tid + i * 256;
        float t = fmaxf(attn[base + cidx] + res[base + cidx], 0.f);
        v[i] = t; s += t;
    }
    const float mean = block_sum_256(s, sh) * (1.0f / UU);

    float vs = 0.f;
#pragma unroll
    for (int i = 0; i < 4; i++) { float d = v[i] - mean; vs += d * d; }
    const float var = block_sum_256(vs, sh) * (1.0f / UU);
    const float inv = rsqrtf(var + LN_EPS);

#pragma unroll
    for (int i = 0; i < 4; i++) {
        int cidx = tid + i * 256;
        out[base + cidx] = gamma[cidx] * ((v[i] - mean) * inv) + beta[cidx];
    }
}

// ---------------------------------------------------------------------------
extern "C" void kernel_launch(void* const* d_in, const int* in_sizes, int n_in,
                              void* d_out, int out_size)
{
    const float* x     = (const float*)d_in[0];
    const float* Wq    = (const float*)d_in[1];
    const float* bq    = (const float*)d_in[2];
    const float* Wk    = (const float*)d_in[3];
    const float* bk    = (const float*)d_in[4];
    const float* Wv    = (const float*)d_in[5];
    const float* bv    = (const float*)d_in[6];
    const float* Wr    = (const float*)d_in[7];
    const float* br_   = (const float*)d_in[8];
    const float* gamma = (const float*)d_in[9];
    const float* beta  = (const float*)d_in[10];
    float* out = (float*)d_out;

    __half *xh, *wth, *qh, *kh, *vh, *vt;
    float *r, *attn;
    cudaGetSymbolAddress((void**)&xh,   g_xh);
    cudaGetSymbolAddress((void**)&wth,  g_wth);
    cudaGetSymbolAddress((void**)&qh,   g_qh);
    cudaGetSymbolAddress((void**)&kh,   g_kh);
    cudaGetSymbolAddress((void**)&vh,   g_vh);
    cudaGetSymbolAddress((void**)&vt,   g_vt);
    cudaGetSymbolAddress((void**)&r,    g_r);
    cudaGetSymbolAddress((void**)&attn, g_attn);

    cudaFuncSetAttribute(gemm_h<true,  true >, cudaFuncAttributeMaxDynamicSharedMemorySize, HGSMEM);
    cudaFuncSetAttribute(gemm_h<true,  false>, cudaFuncAttributeMaxDynamicSharedMemorySize, HGSMEM);
    cudaFuncSetAttribute(flash_h, cudaFuncAttributeMaxDynamicSharedMemorySize, FL_SMEM);

    // 1) fp16 conversions
    cvtx_kernel<<<(MROWS * UU / 4 + 255) / 256, 256>>>(x, xh, MROWS * UU / 4);
    {
        dim3 g(UU / 32, UU / 32);
        cvtWT_kernel<<<g, 256>>>(Wq, wth + 0 * (size_t)UU * UU);
        cvtWT_kernel<<<g, 256>>>(Wk, wth + 1 * (size_t)UU * UU);
        cvtWT_kernel<<<g, 256>>>(Wv, wth + 2 * (size_t)UU * UU);
        cvtWT_kernel<<<g, 256>>>(Wr, wth + 3 * (size_t)UU * UU);
    }

    // 2) projections
    {
        dim3 gr(UU / 128, MROWS / 128, 1);
        gemm_h<true, true ><<<gr, 128, HGSMEM>>>(xh, wth + 0 * (size_t)UU * UU, bq,  qh, UU, UU, UU, 0, 0, 0, UU / 64, QSCALE);
        gemm_h<true, true ><<<gr, 128, HGSMEM>>>(xh, wth + 1 * (size_t)UU * UU, bk,  kh, UU, UU, UU, 0, 0, 0, UU / 64, 1.0f);
        gemm_h<true, true ><<<gr, 128, HGSMEM>>>(xh, wth + 2 * (size_t)UU * UU, bv,  vh, UU, UU, UU, 0, 0, 0, UU / 64, 1.0f);
        gemm_h<true, false><<<gr, 128, HGSMEM>>>(xh, wth + 3 * (size_t)UU * UU, br_, r,  UU, UU, UU, 0, 0, 0, UU / 64, 1.0f);
    }

    // 3) per-head V^T
    transposeV_kernel<<<dim3(HD / 32, SS / 32, NHEAD), 256>>>(vh, vt);

    // 4) fused flash attention
    flash_h<<<dim3(SS / FQB, NHEAD), 256, FL_SMEM>>>(qh, kh, vt, attn);

    // 5) LayerNorm epilogue
    ln_kernel<<<MROWS, 256>>>(attn, r, gamma, beta, out);
}

// round 10
// speedup vs baseline: 5.1152x; 1.1658x over previous
#include <cuda_runtime.h>
#include <cuda_fp16.h>
#include <math.h>
#include <stdint.h>

// ---------------------------------------------------------------------------
// Problem constants
// ---------------------------------------------------------------------------
#define SS 2048
#define UU 1024
#define HD 128
#define NHEAD 32
#define MROWS 8192
#define LN_EPS 1e-8f
#define QSCALE 0.08838834764831845f   // 1/sqrt(128)

// ---------------------------------------------------------------------------
// Scratch (device globals; allocation-free rule)
// ---------------------------------------------------------------------------
__device__ __half g_xh[(size_t)MROWS * UU];
__device__ __half g_wth[4 * (size_t)UU * UU];      // W^T fp16, rows = 4096 outputs
__device__ __half g_qh[(size_t)MROWS * UU];
__device__ __half g_kh[(size_t)MROWS * UU];
__device__ __half g_vh[(size_t)MROWS * UU];
__device__ __half g_vt[(size_t)MROWS * UU];        // per-head V^T [d][s]
__device__ float  g_r[(size_t)MROWS * UU];
__device__ float  g_attn[(size_t)MROWS * UU];

// ---------------------------------------------------------------------------
// Helpers
// ---------------------------------------------------------------------------
__device__ __forceinline__ uint32_t smem_u32(const void* p) {
    uint32_t a;
    asm("{ .reg .u64 t; cvta.to.shared.u64 t, %1; cvt.u32.u64 %0, t; }" : "=r"(a) : "l"(p));
    return a;
}

#define CP_ASYNC16(sa, g) \
    asm volatile("cp.async.cg.shared.global [%0], [%1], 16;" :: "r"(sa), "l"(g))
#define CP_COMMIT() asm volatile("cp.async.commit_group;" ::: "memory")
#define CP_WAIT1()  asm volatile("cp.async.wait_group 1;" ::: "memory")

#define MMA_F16(d, a, b) \
    asm volatile("mma.sync.aligned.m16n8k16.row.col.f32.f16.f16.f32 " \
        "{%0,%1,%2,%3}, {%4,%5,%6,%7}, {%8,%9}, {%0,%1,%2,%3};" \
        : "+f"((d)[0]), "+f"((d)[1]), "+f"((d)[2]), "+f"((d)[3]) \
        : "r"((a)[0]), "r"((a)[1]), "r"((a)[2]), "r"((a)[3]), \
          "r"((b)[0]), "r"((b)[1]))

#define LDSM_X4(r0, r1, r2, r3, sa) \
    asm volatile("ldmatrix.sync.aligned.m8n8.x4.shared.b16 {%0,%1,%2,%3}, [%4];" \
        : "=r"(r0), "=r"(r1), "=r"(r2), "=r"(r3) : "r"(sa))

// pack two fp32 -> one half2 register (lo -> low half)
__device__ __forceinline__ uint32_t pack_h2(float lo, float hi) {
    uint32_t r;
    asm("cvt.rn.f16x2.f32 %0, %1, %2;" : "=r"(r) : "f"(hi), "f"(lo));
    return r;
}

// ---------------------------------------------------------------------------
// Fused projection GEMM: one launch computes q|k|v|r = relu(x @ W + b).
// W^T fused as [4096, 1024] K-major rows. Grid (32 n-blocks, 64 m-blocks).
// 128 threads = 4 warps (2x2), warp tile 64x64, BK=64 halfs, 3-stage cp.async.
// Operand fetch via ldmatrix.x4 (stride 144 B == 36 words == 4 mod 32:
// each 8-row matrix phase covers all 32 banks -> conflict-free).
// ---------------------------------------------------------------------------
#define HSTR 72
#define HROWB 144
#define HA_BYTES (128 * HROWB)
#define HSTAGE (2 * HA_BYTES)
#define HGSMEM (3 * HSTAGE)

__global__ __launch_bounds__(128, 2)
void gemm_proj(const __half* __restrict__ A, const __half* __restrict__ W,
               const float* __restrict__ bq, const float* __restrict__ bk,
               const float* __restrict__ bv, const float* __restrict__ brr,
               __half* __restrict__ qo, __half* __restrict__ ko,
               __half* __restrict__ vo, float* __restrict__ ro)
{
    extern __shared__ __align__(16) char hsm[];
    const uint32_t su = smem_u32(hsm);
    const int tid = threadIdx.x, lane = tid & 31, wid = tid >> 5;
    const int g = lane >> 2, c = lane & 3;
    const int wm0 = (wid >> 1) * 64, wn0 = (wid & 1) * 64;
    const int gm0 = blockIdx.y * 128, gn0 = blockIdx.x * 128;

    const __half* Ab = A + (size_t)gm0 * UU;
    const __half* Bb = W + (size_t)gn0 * UU;

    // ldmatrix per-lane geometry
    const int lrow = lane & 7;
    const int axr = (lane >> 3) & 1, axc = lane >> 4;      // A: row+8, col+8
    const int bxc = (lane >> 3) & 1, bxr = lane >> 4;      // B: col+8, row+8

    uint32_t aOff[4], bOff[4];
#pragma unroll
    for (int mi = 0; mi < 4; mi++)
        aOff[mi] = (uint32_t)((wm0 + mi * 16 + axr * 8 + lrow) * HROWB + axc * 16);
#pragma unroll
    for (int np = 0; np < 4; np++)
        bOff[np] = (uint32_t)(HA_BYTES + (wn0 + np * 16 + bxr * 8 + lrow) * HROWB + bxc * 16);

    float acc[4][8][4];
#pragma unroll
    for (int mi = 0; mi < 4; mi++)
#pragma unroll
        for (int ni = 0; ni < 8; ni++)
#pragma unroll
            for (int t = 0; t < 4; t++) acc[mi][ni][t] = 0.f;

    auto load_tile = [&](int i, int s) {
        const uint32_t abase = su + (uint32_t)(s * HSTAGE);
        const uint32_t bbase = abase + HA_BYTES;
#pragma unroll
        for (int it = 0; it < 8; it++) {
            int chunk = tid + it * 128;
            int row = chunk >> 3, ks = chunk & 7;
            CP_ASYNC16(abase + (uint32_t)(row * HROWB + ks * 16),
                       Ab + (size_t)row * UU + i * 64 + ks * 8);
        }
#pragma unroll
        for (int it = 0; it < 8; it++) {
            int chunk = tid + it * 128;
            int row = chunk >> 3, ks = chunk & 7;
            CP_ASYNC16(bbase + (uint32_t)(row * HROWB + ks * 16),
                       Bb + (size_t)row * UU + i * 64 + ks * 8);
        }
    };

    load_tile(0, 0); CP_COMMIT();
    load_tile(1, 1); CP_COMMIT();

    const int kIters = UU / 64;   // 16
    for (int i = 0; i < kIters; i++) {
        CP_WAIT1();
        __syncthreads();
        if (i + 2 < kIters) load_tile(i + 2, (i + 2) % 3);
        CP_COMMIT();

        const uint32_t sOff = su + (uint32_t)((i % 3) * HSTAGE);

#pragma unroll
        for (int j = 0; j < 4; j++) {
            uint32_t a[4][4], b[8][2];
#pragma unroll
            for (int mi = 0; mi < 4; mi++)
                LDSM_X4(a[mi][0], a[mi][1], a[mi][2], a[mi][3],
                        sOff + aOff[mi] + j * 32);
#pragma unroll
            for (int np = 0; np < 4; np++)
                LDSM_X4(b[2 * np][0], b[2 * np][1], b[2 * np + 1][0], b[2 * np + 1][1],
                        sOff + bOff[np] + j * 32);
#pragma unroll
            for (int mi = 0; mi < 4; mi++)
#pragma unroll
                for (int ni = 0; ni < 8; ni++)
                    MMA_F16(acc[mi][ni], a[mi], b[ni]);
        }
        __syncthreads();
    }

    // ---- epilogue: route to q/k/v (fp16) or r (fp32) ----
    const int which = blockIdx.x >> 3;                  // 0..3
    const int cbase = (blockIdx.x & 7) * 128 + wn0;     // local col in [0,1024)
    const float scale = (which == 0) ? QSCALE : 1.0f;
    const float* bp = (which == 0) ? bq : (which == 1) ? bk : (which == 2) ? bv : brr;
    __half* dsth = (which == 0) ? qo : (which == 1) ? ko : vo;

#pragma unroll
    for (int mi = 0; mi < 4; mi++) {
        const int r0 = gm0 + wm0 + mi * 16 + g;
#pragma unroll
        for (int ni = 0; ni < 8; ni++) {
            const int col = cbase + ni * 8 + c * 2;
            float b0 = __ldg(bp + col), b1 = __ldg(bp + col + 1);
            float v0 = fmaxf(acc[mi][ni][0] + b0, 0.f) * scale;
            float v1 = fmaxf(acc[mi][ni][1] + b1, 0.f) * scale;
            float v2 = fmaxf(acc[mi][ni][2] + b0, 0.f) * scale;
            float v3 = fmaxf(acc[mi][ni][3] + b1, 0.f) * scale;
            if (which < 3) {
                *(__half2*)(dsth + (size_t)r0 * UU + col) = __floats2half2_rn(v0, v1);
                *(__half2*)(dsth + (size_t)(r0 + 8) * UU + col) = __floats2half2_rn(v2, v3);
            } else {
                *(float2*)(ro + (size_t)r0 * UU + col) = make_float2(v0, v1);
                *(float2*)(ro + (size_t)(r0 + 8) * UU + col) = make_float2(v2, v3);
            }
        }
    }
}

// ---------------------------------------------------------------------------
// fp16 flash attention (validated round 9 layout), operands via ldmatrix.
// Q/K stride 272 B (68 words == 4 mod 32 -> conflict-free); V^T stride 144 B.
// ---------------------------------------------------------------------------
#define FQB 128
#define FKB 64
#define FSTR 136
#define FROWB 272
#define FQ_BYTES (FQB * FROWB)                    // 34816
#define FK_BYTES (FKB * FROWB)                    // 17408
#define FV_BYTES (HD * HROWB)                     // 18432
#define FSTAGE (FK_BYTES + FV_BYTES)              // 35840
#define FL_SMEM (FQ_BYTES + 2 * FSTAGE)           // 106496

__global__ __launch_bounds__(256, 2)
void flash_h(const __half* __restrict__ q, const __half* __restrict__ k,
             const __half* __restrict__ vt, float* __restrict__ attn)
{
    extern __shared__ __align__(16) char fsm[];
    const uint32_t su = smem_u32(fsm);
    const int tid = threadIdx.x, lane = tid & 31, wid = tid >> 5;
    const int g = lane >> 2, c = lane & 3;
    const int h = blockIdx.y, qb = blockIdx.x;
    const int wq0 = wid * 16;

    const __half* qh = q + ((size_t)h * SS + (size_t)qb * FQB) * HD;
    const __half* kh = k + (size_t)h * SS * HD;
    const __half* vth = vt + (size_t)h * HD * SS;   // [d][s], ld = SS

    // ldmatrix per-lane geometry
    const int lrow = lane & 7;
    const int axr = (lane >> 3) & 1, axc = lane >> 4;
    const int bxc = (lane >> 3) & 1, bxr = lane >> 4;

    const uint32_t qAddr = su + (uint32_t)((wq0 + axr * 8 + lrow) * FROWB + axc * 16);
    const uint32_t kAddr = su + (uint32_t)(FQ_BYTES + (bxr * 8 + lrow) * FROWB + bxc * 16);
    const uint32_t vAddr = su + (uint32_t)(FQ_BYTES + FK_BYTES + (bxr * 8 + lrow) * HROWB + bxc * 16);

    // ---- stage Q: 128 rows x 16 chunks of 16B (stride 272 B) ----
#pragma unroll
    for (int it = 0; it < 8; it++) {
        int idx = tid + it * 256;
        int row = idx >> 4, ks = idx & 15;
        CP_ASYNC16(su + (uint32_t)(row * FROWB + ks * 16),
                   qh + (size_t)row * HD + ks * 8);
    }
    CP_COMMIT();

    auto load_kv = [&](int i, int s) {
        const __half* kg = kh + (size_t)i * FKB * HD;
        const __half* vg = vth + (size_t)i * FKB;
        const uint32_t kbs = su + (uint32_t)(FQ_BYTES + s * FSTAGE);
        const uint32_t vbs = kbs + FK_BYTES;
#pragma unroll
        for (int it = 0; it < 4; it++) {             // K: 64 rows x 16 chunks
            int idx = tid + it * 256;
            int row = idx >> 4, ks = idx & 15;
            CP_ASYNC16(kbs + (uint32_t)(row * FROWB + ks * 16),
                       kg + (size_t)row * HD + ks * 8);
        }
#pragma unroll
        for (int it = 0; it < 4; it++) {             // V^T: 128 d-rows x 8 chunks
            int idx = tid + it * 256;
            int row = idx >> 3, ks = idx & 7;
            CP_ASYNC16(vbs + (uint32_t)(row * HROWB + ks * 16),
                       vg + (size_t)row * SS + ks * 8);
        }
    };
    load_kv(0, 0); CP_COMMIT();
    load_kv(1, 1); CP_COMMIT();

    float of[16][4];
#pragma unroll
    for (int ni = 0; ni < 16; ni++)
#pragma unroll
        for (int t = 0; t < 4; t++) of[ni][t] = 0.f;
    float rm[2] = {-1e30f, -1e30f};
    float rl[2] = {0.f, 0.f};

    const int nIter = SS / FKB;   // 32

#pragma unroll 1
    for (int i = 0; i < nIter; i++) {
        const uint32_t sOff = (uint32_t)((i & 1) * FSTAGE);
        CP_WAIT1();
        __syncthreads();

        // ---- S = Q(16 rows) @ K^T(64 keys), contraction HD=128 ----
        float sacc[8][4];
#pragma unroll
        for (int ni = 0; ni < 8; ni++)
#pragma unroll
            for (int t = 0; t < 4; t++) sacc[ni][t] = 0.f;

#pragma unroll
        for (int j = 0; j < 8; j++) {
            uint32_t a[4], b[8][2];
            LDSM_X4(a[0], a[1], a[2], a[3], qAddr + j * 32);
#pragma unroll
            for (int np = 0; np < 4; np++)
                LDSM_X4(b[2 * np][0], b[2 * np][1], b[2 * np + 1][0], b[2 * np + 1][1],
                        kAddr + sOff + (uint32_t)(np * 16 * FROWB) + j * 32);
#pragma unroll
            for (int ni = 0; ni < 8; ni++)
                MMA_F16(sacc[ni], a, b[ni]);
        }

        // ---- online softmax (rows g, g+8; reduce over c lanes) ----
        float alpha[2];
#pragma unroll
        for (int hf = 0; hf < 2; hf++) {
            float mx = -1e30f;
#pragma unroll
            for (int ni = 0; ni < 8; ni++) {
                mx = fmaxf(mx, sacc[ni][hf * 2]);
                mx = fmaxf(mx, sacc[ni][hf * 2 + 1]);
            }
            mx = fmaxf(mx, __shfl_xor_sync(0xffffffffu, mx, 1));
            mx = fmaxf(mx, __shfl_xor_sync(0xffffffffu, mx, 2));
            float mn = fmaxf(rm[hf], mx);
            alpha[hf] = __expf(rm[hf] - mn);
            rm[hf] = mn;

            float rs = 0.f;
#pragma unroll
            for (int ni = 0; ni < 8; ni++) {
                float p0 = __expf(sacc[ni][hf * 2]     - mn);
                float p1 = __expf(sacc[ni][hf * 2 + 1] - mn);
                rs += p0 + p1;
                sacc[ni][hf * 2]     = p0;
                sacc[ni][hf * 2 + 1] = p1;
            }
            rs += __shfl_xor_sync(0xffffffffu, rs, 1);
            rs += __shfl_xor_sync(0xffffffffu, rs, 2);
            rl[hf] = rl[hf] * alpha[hf] + rs;
        }

        // ---- rescale O ----
#pragma unroll
        for (int ni = 0; ni < 16; ni++) {
            of[ni][0] *= alpha[0];
            of[ni][1] *= alpha[0];
            of[ni][2] *= alpha[1];
            of[ni][3] *= alpha[1];
        }

        // ---- O += P @ V : A-frags packed from sacc; V frags via ldmatrix ----
#pragma unroll
        for (int jj = 0; jj < 4; jj++) {
            uint32_t a[4];
            a[0] = pack_h2(sacc[2 * jj][0],     sacc[2 * jj][1]);
            a[1] = pack_h2(sacc[2 * jj][2],     sacc[2 * jj][3]);
            a[2] = pack_h2(sacc[2 * jj + 1][0], sacc[2 * jj + 1][1]);
            a[3] = pack_h2(sacc[2 * jj + 1][2], sacc[2 * jj + 1][3]);
#pragma unroll
            for (int np = 0; np < 8; np++) {
                uint32_t b0, b1, b2, b3;
                LDSM_X4(b0, b1, b2, b3,
                        vAddr + sOff + (uint32_t)(np * 16 * HROWB) + jj * 32);
                uint32_t bb0[2] = {b0, b1}, bb1[2] = {b2, b3};
                MMA_F16(of[2 * np], a, bb0);
                MMA_F16(of[2 * np + 1], a, bb1);
            }
        }

        __syncthreads();
        if (i + 2 < nIter) load_kv(i + 2, (i & 1));
        CP_COMMIT();
    }

    // ---- normalize + write ----
    float inv[2] = {1.0f / rl[0], 1.0f / rl[1]};
    float* outb = attn + ((size_t)h * SS + (size_t)qb * FQB + wq0) * HD;
#pragma unroll
    for (int hf = 0; hf < 2; hf++) {
        float* rowp = outb + (size_t)(hf * 8 + g) * HD;
#pragma unroll
        for (int ni = 0; ni < 16; ni++)
            *(float2*)(rowp + ni * 8 + 2 * c) =
                make_float2(of[ni][hf * 2] * inv[hf], of[ni][hf * 2 + 1] * inv[hf]);
    }
}

// ---------------------------------------------------------------------------
// Prep kernels
// ---------------------------------------------------------------------------
__global__ __launch_bounds__(256)
void cvtx_kernel(const float* __restrict__ in, __half* __restrict__ out, int n4)
{
    int i = blockIdx.x * 256 + threadIdx.x;
    if (i < n4) {
        float4 v = ((const float4*)in)[i];
        ((__half2*)out)[2 * i]     = __floats2half2_rn(v.x, v.y);
        ((__half2*)out)[2 * i + 1] = __floats2half2_rn(v.z, v.w);
    }
}

__global__ __launch_bounds__(256)
void cvtWT_kernel(const float* __restrict__ in, __half* __restrict__ out)
{
    __shared__ float t[32][33];
    int k0 = blockIdx.y * 32, n0 = blockIdx.x * 32;
    int tx = threadIdx.x & 31, ty = threadIdx.x >> 5;
#pragma unroll
    for (int r = 0; r < 32; r += 8)
        t[ty + r][tx] = in[(size_t)(k0 + ty + r) * UU + n0 + tx];
    __syncthreads();
#pragma unroll
    for (int r = 0; r < 32; r += 8)
        out[(size_t)(n0 + ty + r) * UU + k0 + tx] = __float2half_rn(t[tx][ty + r]);
}

__global__ __launch_bounds__(256)
void transposeV_kernel(const __half* __restrict__ v, __half* __restrict__ vt)
{
    __shared__ float t[32][33];
    int h = blockIdx.z;
    int d0 = blockIdx.x * 32, s0 = blockIdx.y * 32;
    const __half* vh = v + (size_t)h * SS * HD;
    __half* vth = vt + (size_t)h * HD * SS;
    int tx = threadIdx.x & 31, ty = threadIdx.x >> 5;
#pragma unroll
    for (int r = 0; r < 32; r += 8)
        t[ty + r][tx] = __half2float(vh[(size_t)(s0 + ty + r) * HD + d0 + tx]);
    __syncthreads();
#pragma unroll
    for (int r = 0; r < 32; r += 8)
        vth[(size_t)(d0 + ty + r) * SS + s0 + tx] = __float2half_rn(t[tx][ty + r]);
}

// ---------------------------------------------------------------------------
// Fused epilogue: out = gamma * LN(relu(attn + res)) + beta
// ---------------------------------------------------------------------------
__device__ __forceinline__ float block_sum_256(float v, float* sh)
{
#pragma unroll
    for (int o = 16; o > 0; o >>= 1) v += __shfl_xor_sync(0xffffffffu, v, o);
    if ((threadIdx.x & 31) == 0) sh[threadIdx.x >> 5] = v;
    __syncthreads();
    float t = 0.f;
#pragma unroll
    for (int i = 0; i < 8; i++) t += sh[i];
    __syncthreads();
    return t;
}

__global__ __launch_bounds__(256)
void ln_kernel(const float* __restrict__ attn, const float* __restrict__ res,
               const float* __restrict__ gamma, const float* __restrict__ beta,
               float* __restrict__ out)
{
    __shared__ float sh[8];
    const int tid = threadIdx.x;
    const size_t base = (size_t)blockIdx.x * UU;

    float v[4];
    float s = 0.f;
#pragma unroll
    for (int i = 0; i < 4; i++) {
        int cidx = tid + i * 256;
        float t = fmaxf(attn[base + cidx] + res[base + cidx], 0.f);
        v[i] = t; s += t;
    }
    const float mean = block_sum_256(s, sh) * (1.0f / UU);

    float vs = 0.f;
#pragma unroll
    for (int i = 0; i < 4; i++) { float d = v[i] - mean; vs += d * d; }
    const float var = block_sum_256(vs, sh) * (1.0f / UU);
    const float inv = rsqrtf(var + LN_EPS);

#pragma unroll
    for (int i = 0; i < 4; i++) {
        int cidx = tid + i * 256;
        out[base + cidx] = gamma[cidx] * ((v[i] - mean) * inv) + beta[cidx];
    }
}

// ---------------------------------------------------------------------------
extern "C" void kernel_launch(void* const* d_in, const int* in_sizes, int n_in,
                              void* d_out, int out_size)
{
    const float* x     = (const float*)d_in[0];
    const float* Wq    = (const float*)d_in[1];
    const float* bq    = (const float*)d_in[2];
    const float* Wk    = (const float*)d_in[3];
    const float* bk    = (const float*)d_in[4];
    const float* Wv    = (const float*)d_in[5];
    const float* bv    = (const float*)d_in[6];
    const float* Wr    = (const float*)d_in[7];
    const float* br_   = (const float*)d_in[8];
    const float* gamma = (const float*)d_in[9];
    const float* beta  = (const float*)d_in[10];
    float* out = (float*)d_out;

    __half *xh, *wth, *qh, *kh, *vh, *vt;
    float *r, *attn;
    cudaGetSymbolAddress((void**)&xh,   g_xh);
    cudaGetSymbolAddress((void**)&wth,  g_wth);
    cudaGetSymbolAddress((void**)&qh,   g_qh);
    cudaGetSymbolAddress((void**)&kh,   g_kh);
    cudaGetSymbolAddress((void**)&vh,   g_vh);
    cudaGetSymbolAddress((void**)&vt,   g_vt);
    cudaGetSymbolAddress((void**)&r,    g_r);
    cudaGetSymbolAddress((void**)&attn, g_attn);

    cudaFuncSetAttribute(gemm_proj, cudaFuncAttributeMaxDynamicSharedMemorySize, HGSMEM);
    cudaFuncSetAttribute(flash_h,   cudaFuncAttributeMaxDynamicSharedMemorySize, FL_SMEM);

    // 1) fp16 conversions
    cvtx_kernel<<<(MROWS * UU / 4 + 255) / 256, 256>>>(x, xh, MROWS * UU / 4);
    {
        dim3 g(UU / 32, UU / 32);
        cvtWT_kernel<<<g, 256>>>(Wq, wth + 0 * (size_t)UU * UU);
        cvtWT_kernel<<<g, 256>>>(Wk, wth + 1 * (size_t)UU * UU);
        cvtWT_kernel<<<g, 256>>>(Wv, wth + 2 * (size_t)UU * UU);
        cvtWT_kernel<<<g, 256>>>(Wr, wth + 3 * (size_t)UU * UU);
    }

    // 2) fused projections (q|k|v|r in one launch)
    gemm_proj<<<dim3(4 * UU / 128, MROWS / 128), 128, HGSMEM>>>(
        xh, wth, bq, bk, bv, br_, qh, kh, vh, r);

    // 3) per-head V^T
    transposeV_kernel<<<dim3(HD / 32, SS / 32, NHEAD), 256>>>(vh, vt);

    // 4) fused flash attention
    flash_h<<<dim3(SS / FQB, NHEAD), 256, FL_SMEM>>>(qh, kh, vt, attn);

    // 5) LayerNorm epilogue
    ln_kernel<<<MROWS, 256>>>(attn, r, gamma, beta, out);
}

// round 12
// speedup vs baseline: 5.1988x; 1.0163x over previous
#include <cuda_runtime.h>
#include <cuda_fp16.h>
#include <math.h>
#include <stdint.h>

// ---------------------------------------------------------------------------
// Problem constants
// ---------------------------------------------------------------------------
#define SS 2048
#define UU 1024
#define HD 128
#define NHEAD 32
#define MROWS 8192
#define LN_EPS 1e-8f
#define QSCALE 0.08838834764831845f   // 1/sqrt(128)

// ---------------------------------------------------------------------------
// Scratch (device globals; allocation-free rule)
// ---------------------------------------------------------------------------
__device__ __half g_xh[(size_t)MROWS * UU];
__device__ __half g_wth[4 * (size_t)UU * UU];      // W^T fp16, rows = 4096 outputs
__device__ __half g_qh[(size_t)MROWS * UU];
__device__ __half g_kh[(size_t)MROWS * UU];
__device__ __half g_vh[(size_t)MROWS * UU];
__device__ __half g_vt[(size_t)MROWS * UU];        // per-head V^T [d][s]
__device__ float  g_r[(size_t)MROWS * UU];
__device__ float  g_attn[(size_t)MROWS * UU];

// ---------------------------------------------------------------------------
// Helpers
// ---------------------------------------------------------------------------
__device__ __forceinline__ uint32_t smem_u32(const void* p) {
    uint32_t a;
    asm("{ .reg .u64 t; cvta.to.shared.u64 t, %1; cvt.u32.u64 %0, t; }" : "=r"(a) : "l"(p));
    return a;
}

#define CP_ASYNC16(sa, g) \
    asm volatile("cp.async.cg.shared.global [%0], [%1], 16;" :: "r"(sa), "l"(g))
#define CP_COMMIT() asm volatile("cp.async.commit_group;" ::: "memory")
#define CP_WAIT1()  asm volatile("cp.async.wait_group 1;" ::: "memory")

#define MMA_F16(d, a, b) \
    asm volatile("mma.sync.aligned.m16n8k16.row.col.f32.f16.f16.f32 " \
        "{%0,%1,%2,%3}, {%4,%5,%6,%7}, {%8,%9}, {%0,%1,%2,%3};" \
        : "+f"((d)[0]), "+f"((d)[1]), "+f"((d)[2]), "+f"((d)[3]) \
        : "r"((a)[0]), "r"((a)[1]), "r"((a)[2]), "r"((a)[3]), \
          "r"((b)[0]), "r"((b)[1]))

#define LDSM_X4(r0, r1, r2, r3, sa) \
    asm volatile("ldmatrix.sync.aligned.m8n8.x4.shared.b16 {%0,%1,%2,%3}, [%4];" \
        : "=r"(r0), "=r"(r1), "=r"(r2), "=r"(r3) : "r"(sa))

// pack two fp32 -> one half2 register (lo -> low half)
__device__ __forceinline__ uint32_t pack_h2(float lo, float hi) {
    uint32_t r;
    asm("cvt.rn.f16x2.f32 %0, %1, %2;" : "=r"(r) : "f"(hi), "f"(lo));
    return r;
}

// ---------------------------------------------------------------------------
// Fused projection GEMM: one launch computes q|k|v|r = relu(x @ W + b).
// W^T fused as [4096, 1024] K-major rows. Grid (32 n-blocks, 64 m-blocks).
// 256 threads = 8 warps (2x4), warp tile 64x32, BK=64 halfs, 3-stage cp.async.
// 2 CTAs/SM -> 16 warps/SM = 4 warps/SMSP.
// ---------------------------------------------------------------------------
#define HSTR 72
#define HROWB 144
#define HA_BYTES (128 * HROWB)
#define HSTAGE (2 * HA_BYTES)
#define HGSMEM (3 * HSTAGE)

__global__ __launch_bounds__(256, 2)
void gemm_proj(const __half* __restrict__ A, const __half* __restrict__ W,
               const float* __restrict__ bq, const float* __restrict__ bk,
               const float* __restrict__ bv, const float* __restrict__ brr,
               __half* __restrict__ qo, __half* __restrict__ ko,
               __half* __restrict__ vo, float* __restrict__ ro)
{
    extern __shared__ __align__(16) char hsm[];
    const uint32_t su = smem_u32(hsm);
    const int tid = threadIdx.x, lane = tid & 31, wid = tid >> 5;
    const int g = lane >> 2, c = lane & 3;
    const int wm0 = (wid >> 2) * 64, wn0 = (wid & 3) * 32;
    const int gm0 = blockIdx.y * 128;

    const __half* Ab = A + (size_t)gm0 * UU;
    const __half* Bb = W + (size_t)blockIdx.x * 128 * UU;

    // ldmatrix per-lane geometry
    const int lrow = lane & 7;
    const int axr = (lane >> 3) & 1, axc = lane >> 4;      // A: row+8, col+8
    const int bxc = (lane >> 3) & 1, bxr = lane >> 4;      // B: col+8, row+8

    uint32_t aOff[4], bOff[2];
#pragma unroll
    for (int mi = 0; mi < 4; mi++)
        aOff[mi] = (uint32_t)((wm0 + mi * 16 + axr * 8 + lrow) * HROWB + axc * 16);
#pragma unroll
    for (int np = 0; np < 2; np++)
        bOff[np] = (uint32_t)(HA_BYTES + (wn0 + np * 16 + bxr * 8 + lrow) * HROWB + bxc * 16);

    float acc[4][4][4];
#pragma unroll
    for (int mi = 0; mi < 4; mi++)
#pragma unroll
        for (int ni = 0; ni < 4; ni++)
#pragma unroll
            for (int t = 0; t < 4; t++) acc[mi][ni][t] = 0.f;

    auto load_tile = [&](int i, int s) {
        const uint32_t abase = su + (uint32_t)(s * HSTAGE);
        const uint32_t bbase = abase + HA_BYTES;
#pragma unroll
        for (int it = 0; it < 4; it++) {
            int chunk = tid + it * 256;
            int row = chunk >> 3, ks = chunk & 7;
            CP_ASYNC16(abase + (uint32_t)(row * HROWB + ks * 16),
                       Ab + (size_t)row * UU + i * 64 + ks * 8);
        }
#pragma unroll
        for (int it = 0; it < 4; it++) {
            int chunk = tid + it * 256;
            int row = chunk >> 3, ks = chunk & 7;
            CP_ASYNC16(bbase + (uint32_t)(row * HROWB + ks * 16),
                       Bb + (size_t)row * UU + i * 64 + ks * 8);
        }
    };

    load_tile(0, 0); CP_COMMIT();
    load_tile(1, 1); CP_COMMIT();

    const int kIters = UU / 64;   // 16
    for (int i = 0; i < kIters; i++) {
        CP_WAIT1();
        __syncthreads();
        if (i + 2 < kIters) load_tile(i + 2, (i + 2) % 3);
        CP_COMMIT();

        const uint32_t sOff = su + (uint32_t)((i % 3) * HSTAGE);

#pragma unroll
        for (int j = 0; j < 4; j++) {
            uint32_t a[4][4], b[4][2];
#pragma unroll
            for (int mi = 0; mi < 4; mi++)
                LDSM_X4(a[mi][0], a[mi][1], a[mi][2], a[mi][3],
                        sOff + aOff[mi] + j * 32);
#pragma unroll
            for (int np = 0; np < 2; np++)
                LDSM_X4(b[2 * np][0], b[2 * np][1], b[2 * np + 1][0], b[2 * np + 1][1],
                        sOff + bOff[np] + j * 32);
#pragma unroll
            for (int mi = 0; mi < 4; mi++)
#pragma unroll
                for (int ni = 0; ni < 4; ni++)
                    MMA_F16(acc[mi][ni], a[mi], b[ni]);
        }
        __syncthreads();
    }

    // ---- epilogue: route to q/k/v (fp16) or r (fp32) ----
    const int which = blockIdx.x >> 3;                  // 0..3
    const int cbase = (blockIdx.x & 7) * 128 + wn0;     // local col in [0,1024)
    const float scale = (which == 0) ? QSCALE : 1.0f;
    const float* bp = (which == 0) ? bq : (which == 1) ? bk : (which == 2) ? bv : brr;
    __half* dsth = (which == 0) ? qo : (which == 1) ? ko : vo;

#pragma unroll
    for (int mi = 0; mi < 4; mi++) {
        const int r0 = gm0 + wm0 + mi * 16 + g;
#pragma unroll
        for (int ni = 0; ni < 4; ni++) {
            const int col = cbase + ni * 8 + c * 2;
            float b0 = __ldg(bp + col), b1 = __ldg(bp + col + 1);
            float v0 = fmaxf(acc[mi][ni][0] + b0, 0.f) * scale;
            float v1 = fmaxf(acc[mi][ni][1] + b1, 0.f) * scale;
            float v2 = fmaxf(acc[mi][ni][2] + b0, 0.f) * scale;
            float v3 = fmaxf(acc[mi][ni][3] + b1, 0.f) * scale;
            if (which < 3) {
                *(__half2*)(dsth + (size_t)r0 * UU + col) = __floats2half2_rn(v0, v1);
                *(__half2*)(dsth + (size_t)(r0 + 8) * UU + col) = __floats2half2_rn(v2, v3);
            } else {
                *(float2*)(ro + (size_t)r0 * UU + col) = make_float2(v0, v1);
                *(float2*)(ro + (size_t)(r0 + 8) * UU + col) = make_float2(v2, v3);
            }
        }
    }
}

// ---------------------------------------------------------------------------
// fp16 flash attention (validated round 10).
// ---------------------------------------------------------------------------
#define FQB 128
#define FKB 64
#define FSTR 136
#define FROWB 272
#define FQ_BYTES (FQB * FROWB)                    // 34816
#define FK_BYTES (FKB * FROWB)                    // 17408
#define FV_BYTES (HD * HROWB)                     // 18432
#define FSTAGE (FK_BYTES + FV_BYTES)              // 35840
#define FL_SMEM (FQ_BYTES + 2 * FSTAGE)           // 106496

__global__ __launch_bounds__(256, 2)
void flash_h(const __half* __restrict__ q, const __half* __restrict__ k,
             const __half* __restrict__ vt, float* __restrict__ attn)
{
    extern __shared__ __align__(16) char fsm[];
    const uint32_t su = smem_u32(fsm);
    const int tid = threadIdx.x, lane = tid & 31, wid = tid >> 5;
    const int g = lane >> 2, c = lane & 3;
    const int h = blockIdx.y, qb = blockIdx.x;
    const int wq0 = wid * 16;

    const __half* qh = q + ((size_t)h * SS + (size_t)qb * FQB) * HD;
    const __half* kh = k + (size_t)h * SS * HD;
    const __half* vth = vt + (size_t)h * HD * SS;   // [d][s], ld = SS

    const int lrow = lane & 7;
    const int axr = (lane >> 3) & 1, axc = lane >> 4;
    const int bxc = (lane >> 3) & 1, bxr = lane >> 4;

    const uint32_t qAddr = su + (uint32_t)((wq0 + axr * 8 + lrow) * FROWB + axc * 16);
    const uint32_t kAddr = su + (uint32_t)(FQ_BYTES + (bxr * 8 + lrow) * FROWB + bxc * 16);
    const uint32_t vAddr = su + (uint32_t)(FQ_BYTES + FK_BYTES + (bxr * 8 + lrow) * HROWB + bxc * 16);

    // ---- stage Q: 128 rows x 16 chunks of 16B (stride 272 B) ----
#pragma unroll
    for (int it = 0; it < 8; it++) {
        int idx = tid + it * 256;
        int row = idx >> 4, ks = idx & 15;
        CP_ASYNC16(su + (uint32_t)(row * FROWB + ks * 16),
                   qh + (size_t)row * HD + ks * 8);
    }
    CP_COMMIT();

    auto load_kv = [&](int i, int s) {
        const __half* kg = kh + (size_t)i * FKB * HD;
        const __half* vg = vth + (size_t)i * FKB;
        const uint32_t kbs = su + (uint32_t)(FQ_BYTES + s * FSTAGE);
        const uint32_t vbs = kbs + FK_BYTES;
#pragma unroll
        for (int it = 0; it < 4; it++) {             // K: 64 rows x 16 chunks
            int idx = tid + it * 256;
            int row = idx >> 4, ks = idx & 15;
            CP_ASYNC16(kbs + (uint32_t)(row * FROWB + ks * 16),
                       kg + (size_t)row * HD + ks * 8);
        }
#pragma unroll
        for (int it = 0; it < 4; it++) {             // V^T: 128 d-rows x 8 chunks
            int idx = tid + it * 256;
            int row = idx >> 3, ks = idx & 7;
            CP_ASYNC16(vbs + (uint32_t)(row * HROWB + ks * 16),
                       vg + (size_t)row * SS + ks * 8);
        }
    };
    load_kv(0, 0); CP_COMMIT();
    load_kv(1, 1); CP_COMMIT();

    float of[16][4];
#pragma unroll
    for (int ni = 0; ni < 16; ni++)
#pragma unroll
        for (int t = 0; t < 4; t++) of[ni][t] = 0.f;
    float rm[2] = {-1e30f, -1e30f};
    float rl[2] = {0.f, 0.f};

    const int nIter = SS / FKB;   // 32

#pragma unroll 1
    for (int i = 0; i < nIter; i++) {
        const uint32_t sOff = (uint32_t)((i & 1) * FSTAGE);
        CP_WAIT1();
        __syncthreads();

        // ---- S = Q(16 rows) @ K^T(64 keys), contraction HD=128 ----
        float sacc[8][4];
#pragma unroll
        for (int ni = 0; ni < 8; ni++)
#pragma unroll
            for (int t = 0; t < 4; t++) sacc[ni][t] = 0.f;

#pragma unroll
        for (int j = 0; j < 8; j++) {
            uint32_t a[4], b[8][2];
            LDSM_X4(a[0], a[1], a[2], a[3], qAddr + j * 32);
#pragma unroll
            for (int np = 0; np < 4; np++)
                LDSM_X4(b[2 * np][0], b[2 * np][1], b[2 * np + 1][0], b[2 * np + 1][1],
                        kAddr + sOff + (uint32_t)(np * 16 * FROWB) + j * 32);
#pragma unroll
            for (int ni = 0; ni < 8; ni++)
                MMA_F16(sacc[ni], a, b[ni]);
        }

        // ---- online softmax (rows g, g+8; reduce over c lanes) ----
        float alpha[2];
#pragma unroll
        for (int hf = 0; hf < 2; hf++) {
            float mx = -1e30f;
#pragma unroll
            for (int ni = 0; ni < 8; ni++) {
                mx = fmaxf(mx, sacc[ni][hf * 2]);
                mx = fmaxf(mx, sacc[ni][hf * 2 + 1]);
            }
            mx = fmaxf(mx, __shfl_xor_sync(0xffffffffu, mx, 1));
            mx = fmaxf(mx, __shfl_xor_sync(0xffffffffu, mx, 2));
            float mn = fmaxf(rm[hf], mx);
            alpha[hf] = __expf(rm[hf] - mn);
            rm[hf] = mn;

            float rs = 0.f;
#pragma unroll
            for (int ni = 0; ni < 8; ni++) {
                float p0 = __expf(sacc[ni][hf * 2]     - mn);
                float p1 = __expf(sacc[ni][hf * 2 + 1] - mn);
                rs += p0 + p1;
                sacc[ni][hf * 2]     = p0;
                sacc[ni][hf * 2 + 1] = p1;
            }
            rs += __shfl_xor_sync(0xffffffffu, rs, 1);
            rs += __shfl_xor_sync(0xffffffffu, rs, 2);
            rl[hf] = rl[hf] * alpha[hf] + rs;
        }

        // ---- rescale O ----
#pragma unroll
        for (int ni = 0; ni < 16; ni++) {
            of[ni][0] *= alpha[0];
            of[ni][1] *= alpha[0];
            of[ni][2] *= alpha[1];
            of[ni][3] *= alpha[1];
        }

        // ---- O += P @ V : A-frags packed from sacc; V frags via ldmatrix ----
#pragma unroll
        for (int jj = 0; jj < 4; jj++) {
            uint32_t a[4];
            a[0] = pack_h2(sacc[2 * jj][0],     sacc[2 * jj][1]);
            a[1] = pack_h2(sacc[2 * jj][2],     sacc[2 * jj][3]);
            a[2] = pack_h2(sacc[2 * jj + 1][0], sacc[2 * jj + 1][1]);
            a[3] = pack_h2(sacc[2 * jj + 1][2], sacc[2 * jj + 1][3]);
#pragma unroll
            for (int np = 0; np < 8; np++) {
                uint32_t b0, b1, b2, b3;
                LDSM_X4(b0, b1, b2, b3,
                        vAddr + sOff + (uint32_t)(np * 16 * HROWB) + jj * 32);
                uint32_t bb0[2] = {b0, b1}, bb1[2] = {b2, b3};
                MMA_F16(of[2 * np], a, bb0);
                MMA_F16(of[2 * np + 1], a, bb1);
            }
        }

        __syncthreads();
        if (i + 2 < nIter) load_kv(i + 2, (i & 1));
        CP_COMMIT();
    }

    // ---- normalize + write ----
    float inv[2] = {1.0f / rl[0], 1.0f / rl[1]};
    float* outb = attn + ((size_t)h * SS + (size_t)qb * FQB + wq0) * HD;
#pragma unroll
    for (int hf = 0; hf < 2; hf++) {
        float* rowp = outb + (size_t)(hf * 8 + g) * HD;
#pragma unroll
        for (int ni = 0; ni < 16; ni++)
            *(float2*)(rowp + ni * 8 + 2 * c) =
                make_float2(of[ni][hf * 2] * inv[hf], of[ni][hf * 2 + 1] * inv[hf]);
    }
}

// ---------------------------------------------------------------------------
// Prep kernels
// ---------------------------------------------------------------------------
__global__ __launch_bounds__(256)
void cvtx_kernel(const float* __restrict__ in, __half* __restrict__ out, int n4)
{
    int i = blockIdx.x * 256 + threadIdx.x;
    if (i < n4) {
        float4 v = ((const float4*)in)[i];
        ((__half2*)out)[2 * i]     = __floats2half2_rn(v.x, v.y);
        ((__half2*)out)[2 * i + 1] = __floats2half2_rn(v.z, v.w);
    }
}

__global__ __launch_bounds__(256)
void cvtWT_all(const float* __restrict__ W0, const float* __restrict__ W1,
               const float* __restrict__ W2, const float* __restrict__ W3,
               __half* __restrict__ out)
{
    __shared__ float t[32][33];
    const int z = blockIdx.z;
    const float* in = (z == 0) ? W0 : (z == 1) ? W1 : (z == 2) ? W2 : W3;
    __half* o = out + (size_t)z * UU * UU;
    int k0 = blockIdx.y * 32, n0 = blockIdx.x * 32;
    int tx = threadIdx.x & 31, ty = threadIdx.x >> 5;
#pragma unroll
    for (int r = 0; r < 32; r += 8)
        t[ty + r][tx] = in[(size_t)(k0 + ty + r) * UU + n0 + tx];
    __syncthreads();
#pragma unroll
    for (int r = 0; r < 32; r += 8)
        o[(size_t)(n0 + ty + r) * UU + k0 + tx] = __float2half_rn(t[tx][ty + r]);
}

__global__ __launch_bounds__(256)
void transposeV_kernel(const __half* __restrict__ v, __half* __restrict__ vt)
{   // per head h (raw-reshape contiguous view): vt[h][d][s] = v[h][s][d]
    __shared__ float t[32][33];
    int h = blockIdx.z;
    int d0 = blockIdx.x * 32, s0 = blockIdx.y * 32;
    const __half* vh = v + (size_t)h * SS * HD;
    __half* vth = vt + (size_t)h * HD * SS;
    int tx = threadIdx.x & 31, ty = threadIdx.x >> 5;
#pragma unroll
    for (int r = 0; r < 32; r += 8)
        t[ty + r][tx] = __half2float(vh[(size_t)(s0 + ty + r) * HD + d0 + tx]);
    __syncthreads();
#pragma unroll
    for (int r = 0; r < 32; r += 8)
        vth[(size_t)(d0 + ty + r) * SS + s0 + tx] = __float2half_rn(t[tx][ty + r]);
}

// ---------------------------------------------------------------------------
// Fused epilogue: out = gamma * LN(relu(attn + res)) + beta
// ---------------------------------------------------------------------------
__device__ __forceinline__ float block_sum_256(float v, float* sh)
{
#pragma unroll
    for (int o = 16; o > 0; o >>= 1) v += __shfl_xor_sync(0xffffffffu, v, o);
    if ((threadIdx.x & 31) == 0) sh[threadIdx.x >> 5] = v;
    __syncthreads();
    float t = 0.f;
#pragma unroll
    for (int i = 0; i < 8; i++) t += sh[i];
    __syncthreads();
    return t;
}

__global__ __launch_bounds__(256)
void ln_kernel(const float* __restrict__ attn, const float* __restrict__ res,
               const float* __restrict__ gamma, const float* __restrict__ beta,
               float* __restrict__ out)
{
    __shared__ float sh[8];
    const int tid = threadIdx.x;
    const size_t base = (size_t)blockIdx.x * UU;

    float v[4];
    float s = 0.f;
#pragma unroll
    for (int i = 0; i < 4; i++) {
        int cidx = tid + i * 256;
        float t = fmaxf(attn[base + cidx] + res[base + cidx], 0.f);
        v[i] = t; s += t;
    }
    const float mean = block_sum_256(s, sh) * (1.0f / UU);

    float vs = 0.f;
#pragma unroll
    for (int i = 0; i < 4; i++) { float d = v[i] - mean; vs += d * d; }
    const float var = block_sum_256(vs, sh) * (1.0f / UU);
    const float inv = rsqrtf(var + LN_EPS);

#pragma unroll
    for (int i = 0; i < 4; i++) {
        int cidx = tid + i * 256;
        out[base + cidx] = gamma[cidx] * ((v[i] - mean) * inv) + beta[cidx];
    }
}

// ---------------------------------------------------------------------------
extern "C" void kernel_launch(void* const* d_in, const int* in_sizes, int n_in,
                              void* d_out, int out_size)
{
    const float* x     = (const float*)d_in[0];
    const float* Wq    = (const float*)d_in[1];
    const float* bq    = (const float*)d_in[2];
    const float* Wk    = (const float*)d_in[3];
    const float* bk    = (const float*)d_in[4];
    const float* Wv    = (const float*)d_in[5];
    const float* bv    = (const float*)d_in[6];
    const float* Wr    = (const float*)d_in[7];
    const float* br_   = (const float*)d_in[8];
    const float* gamma = (const float*)d_in[9];
    const float* beta  = (const float*)d_in[10];
    float* out = (float*)d_out;

    __half *xh, *wth, *qh, *kh, *vh, *vt;
    float *r, *attn;
    cudaGetSymbolAddress((void**)&xh,   g_xh);
    cudaGetSymbolAddress((void**)&wth,  g_wth);
    cudaGetSymbolAddress((void**)&qh,   g_qh);
    cudaGetSymbolAddress((void**)&kh,   g_kh);
    cudaGetSymbolAddress((void**)&vh,   g_vh);
    cudaGetSymbolAddress((void**)&vt,   g_vt);
    cudaGetSymbolAddress((void**)&r,    g_r);
    cudaGetSymbolAddress((void**)&attn, g_attn);

    cudaFuncSetAttribute(gemm_proj, cudaFuncAttributeMaxDynamicSharedMemorySize, HGSMEM);
    cudaFuncSetAttribute(flash_h,   cudaFuncAttributeMaxDynamicSharedMemorySize, FL_SMEM);

    // 1) fp16 conversions (2 launches)
    cvtx_kernel<<<(MROWS * UU / 4 + 255) / 256, 256>>>(x, xh, MROWS * UU / 4);
    cvtWT_all<<<dim3(UU / 32, UU / 32, 4), 256>>>(Wq, Wk, Wv, Wr, wth);

    // 2) fused projections (q|k|v|r in one launch)
    gemm_proj<<<dim3(4 * UU / 128, MROWS / 128), 256, HGSMEM>>>(
        xh, wth, bq, bk, bv, br_, qh, kh, vh, r);

    // 3) per-head V^T (raw-reshape contiguous view; validated round 6)
    transposeV_kernel<<<dim3(HD / 32, SS / 32, NHEAD), 256>>>(vh, vt);

    // 4) fused flash attention
    flash_h<<<dim3(SS / FQB, NHEAD), 256, FL_SMEM>>>(qh, kh, vt, attn);

    // 5) LayerNorm epilogue
    ln_kernel<<<MROWS, 256>>>(attn, r, gamma, beta, out);
}